// round 7
// baseline (speedup 1.0000x reference)
#include <cuda_runtime.h>
#include <stdint.h>
#include <math.h>

#define B_    2
#define T_    2048
#define H_    8
#define DK_   64
#define DIN_  512
#define DOUT_ 512
#define BH_   (B_ * H_)

// Scratch (__device__ globals per allocation-free rule)
// g_qh/g_kh: head-dim PERMUTED within 8-groups (s(d)=2*(d&3)+((d&7)>>2)).
// g_vh/g_oh: standard layout. g_w: key-dim permuted within 8-groups.
__device__ float g_qh[BH_ * T_ * DK_];
__device__ float g_kh[BH_ * T_ * DK_];
__device__ float g_vh[BH_ * T_ * DK_];
__device__ float g_oh[BH_ * T_ * DK_];
__device__ float g_w[67108864];          // 256 MB [bh][q][k-perm]

// ---------------------------------------------------------------------------
// helpers
// ---------------------------------------------------------------------------
__device__ __forceinline__ uint32_t f2tf(float f) {
    uint32_t u;
    asm("cvt.rna.tf32.f32 %0, %1;" : "=r"(u) : "f"(f));
    return u;
}
__device__ __forceinline__ uint4 f2tf4(float4 v) {
    uint4 u;
    u.x = f2tf(v.x); u.y = f2tf(v.y); u.z = f2tf(v.z); u.w = f2tf(v.w);
    return u;
}
__device__ __forceinline__ void split3(float x, uint32_t& hi, uint32_t& lo) {
    uint32_t h = f2tf(x);
    hi = h;
    lo = f2tf(x - __uint_as_float(h));
}
// D = A(16x8,row) * B(8x8,col) + D, tf32 operands, f32 accum
__device__ __forceinline__ void mma8(float c[4], uint32_t a0, uint32_t a1,
                                     uint32_t a2, uint32_t a3,
                                     uint32_t b0, uint32_t b1) {
    asm volatile(
        "mma.sync.aligned.m16n8k8.row.col.f32.tf32.tf32.f32 "
        "{%0,%1,%2,%3},{%4,%5,%6,%7},{%8,%9},{%0,%1,%2,%3};\n"
        : "+f"(c[0]), "+f"(c[1]), "+f"(c[2]), "+f"(c[3])
        : "r"(a0), "r"(a1), "r"(a2), "r"(a3), "r"(b0), "r"(b1));
}

#define PROJ_SMEM_BYTES ((128*36*2 + 64*36*2) * 4)       // 55296
#define ATTN_SMEM_BYTES ((256*68 + 128) * 4)             // 70144

// ---------------------------------------------------------------------------
// Kernel 1: fused QKV projection. Q/K 3xTF32, V single tf32.
// Smem k-dim stored permuted -> fragment pairs are LDS.64.
// Q/K epilogue writes head-dim permuted to gmem.
// ---------------------------------------------------------------------------
__global__ __launch_bounds__(256, 2) void proj_kernel(
    const float* __restrict__ qx, const float* __restrict__ kx, const float* __restrict__ vx,
    const float* __restrict__ Wq, const float* __restrict__ bq,
    const float* __restrict__ Wk, const float* __restrict__ bk,
    const float* __restrict__ Wv, const float* __restrict__ bv)
{
    extern __shared__ uint32_t smp[];
    uint32_t* Xh = smp;                 // [128][36], k-permuted
    uint32_t* Xl = Xh + 128 * 36;
    uint32_t* Wh = Xl + 128 * 36;       // [64][36], k-permuted
    uint32_t* Wl = Wh + 64 * 36;

    const float *x, *W, *bias;
    float* out;
    if (blockIdx.z == 0)      { x = qx; W = Wq; bias = bq; out = g_qh; }
    else if (blockIdx.z == 1) { x = kx; W = Wk; bias = bk; out = g_kh; }
    else                      { x = vx; W = Wv; bias = bv; out = g_vh; }
    const bool precise = (blockIdx.z < 2);

    const int tid  = threadIdx.x;
    const int lane = tid & 31, w = tid >> 5;
    const int g = lane >> 2, t4 = lane & 3;
    const int m0 = blockIdx.y * 128;
    const int n0 = blockIdx.x * 64;

    float acc[8][4];
    #pragma unroll
    for (int i = 0; i < 8; i++)
        #pragma unroll
        for (int j = 0; j < 4; j++) acc[i][j] = 0.f;

    for (int k0 = 0; k0 < DIN_; k0 += 32) {
        __syncthreads();
        #pragma unroll
        for (int e = 0; e < 4; e++) {              // X tile 128x32 (k-perm scatter)
            int idx = e * 256 + tid;
            int r = idx >> 3, c4 = (idx & 7) * 4;
            int p0 = r * 36 + (c4 & ~7) + ((c4 & 4) >> 2);
            float4 xv = *(const float4*)&x[(size_t)(m0 + r) * DIN_ + k0 + c4];
            uint4 h, l;
            split3(xv.x, h.x, l.x); split3(xv.y, h.y, l.y);
            split3(xv.z, h.z, l.z); split3(xv.w, h.w, l.w);
            Xh[p0] = h.x; Xh[p0+2] = h.y; Xh[p0+4] = h.z; Xh[p0+6] = h.w;
            Xl[p0] = l.x; Xl[p0+2] = l.y; Xl[p0+4] = l.z; Xl[p0+6] = l.w;
        }
        #pragma unroll
        for (int e = 0; e < 2; e++) {              // W tile 64x32 (k-perm scatter)
            int idx = e * 256 + tid;
            int r = idx >> 3, c4 = (idx & 7) * 4;
            int p0 = r * 36 + (c4 & ~7) + ((c4 & 4) >> 2);
            float4 wv = *(const float4*)&W[(size_t)(n0 + r) * DIN_ + k0 + c4];
            uint4 h, l;
            split3(wv.x, h.x, l.x); split3(wv.y, h.y, l.y);
            split3(wv.z, h.z, l.z); split3(wv.w, h.w, l.w);
            Wh[p0] = h.x; Wh[p0+2] = h.y; Wh[p0+4] = h.z; Wh[p0+6] = h.w;
            Wl[p0] = l.x; Wl[p0+2] = l.y; Wl[p0+4] = l.z; Wl[p0+6] = l.w;
        }
        __syncthreads();

        // A-frags: pairs (a0,a2)/(a1,a3) are adjacent under k-perm -> LDS.64
        uint2 ah02[4], ah13[4], al02[4], al13[4];
        const int r0 = (16 * w + g) * 36, r1 = r0 + 8 * 36;
        #pragma unroll
        for (int kc = 0; kc < 4; kc++) {
            ah02[kc] = *(const uint2*)&Xh[r0 + kc * 8 + 2 * t4];
            ah13[kc] = *(const uint2*)&Xh[r1 + kc * 8 + 2 * t4];
            al02[kc] = *(const uint2*)&Xl[r0 + kc * 8 + 2 * t4];
            al13[kc] = *(const uint2*)&Xl[r1 + kc * 8 + 2 * t4];
        }
        #pragma unroll
        for (int kc = 0; kc < 4; kc++) {
            uint2 bhv[8];
            #pragma unroll
            for (int nc = 0; nc < 8; nc++) {
                bhv[nc] = *(const uint2*)&Wh[(nc * 8 + g) * 36 + kc * 8 + 2 * t4];
                mma8(acc[nc], ah02[kc].x, ah13[kc].x, ah02[kc].y, ah13[kc].y,
                     bhv[nc].x, bhv[nc].y);
            }
            if (precise) {
                #pragma unroll
                for (int nc = 0; nc < 8; nc++) {
                    uint2 blv = *(const uint2*)&Wl[(nc * 8 + g) * 36 + kc * 8 + 2 * t4];
                    mma8(acc[nc], ah02[kc].x, ah13[kc].x, ah02[kc].y, ah13[kc].y,
                         blv.x, blv.y);                       // hi*lo
                }
                #pragma unroll
                for (int nc = 0; nc < 8; nc++)
                    mma8(acc[nc], al02[kc].x, al13[kc].x, al02[kc].y, al13[kc].y,
                         bhv[nc].x, bhv[nc].y);               // lo*hi
            }
        }
    }

    const int h = n0 >> 6;
    const int mA = m0 + 16 * w + g;
    const int bA = mA >> 11, tA = mA & (T_ - 1);
    const int mBr = mA + 8;
    const int bB = mBr >> 11, tB = mBr & (T_ - 1);
    float* rowA = out + ((size_t)(bA * H_ + h) * T_ + tA) * DK_;
    float* rowB = out + ((size_t)(bB * H_ + h) * T_ + tB) * DK_;
    if (precise) {
        // Q/K: store head-dim permuted: logical cols (2t4, 2t4+1) -> (b, b+2)
        const int bcol = ((t4 & 1) << 2) + (t4 >> 1);
        #pragma unroll
        for (int nc = 0; nc < 8; nc++) {
            int colL = nc * 8 + 2 * t4;           // logical (for bias)
            int colS = nc * 8 + bcol;             // storage
            float bx = bias[n0 + colL], by = bias[n0 + colL + 1];
            rowA[colS]     = acc[nc][0] + bx;
            rowA[colS + 2] = acc[nc][1] + by;
            rowB[colS]     = acc[nc][2] + bx;
            rowB[colS + 2] = acc[nc][3] + by;
        }
    } else {
        #pragma unroll
        for (int nc = 0; nc < 8; nc++) {
            int col = nc * 8 + 2 * t4;
            float bx = bias[n0 + col], by = bias[n0 + col + 1];
            *(float2*)&rowA[col] = make_float2(acc[nc][0] + bx, acc[nc][1] + by);
            *(float2*)&rowB[col] = make_float2(acc[nc][2] + bx, acc[nc][3] + by);
        }
    }
}

// ---------------------------------------------------------------------------
// Kernel 2: attention. Q/K arrive head-dim-permuted -> STS.128 staging and
// LDS.64 fragment pairs everywhere in QK. w stored key-permuted in g_w;
// pass 2 P-frags LDS.64. V standard.
// ---------------------------------------------------------------------------
__global__ __launch_bounds__(256, 2) void attn_kernel()
{
    extern __shared__ uint32_t sma[];
    uint32_t* Kh  = sma;                  // [64][68]
    uint32_t* Kl  = Kh + 64 * 68;
    uint32_t* Qlo = sma + 128 * 68;       // [128][68], persists through pass 1
    uint32_t* Qhi = sma;                  // staging (over Kh+Kl)
    uint32_t* Ps  = sma;                  // pass2 [128][68] (over Kh+Kl)
    uint32_t* Vs  = sma + 128 * 68;       // pass2 [64][68]  (over Qlo)
    float*  thr_s = (float*)(sma + 256 * 68);   // [128]

    const int bh = blockIdx.x;
    const int q0 = blockIdx.y * 128;
    const float* qh = g_qh + (size_t)bh * T_ * DK_;
    const float* kh = g_kh + (size_t)bh * T_ * DK_;
    const float* vh = g_vh + (size_t)bh * T_ * DK_;
    float* wb = g_w + (size_t)bh * T_ * T_;
    float* oh = g_oh + (size_t)bh * T_ * DK_;

    const int tid  = threadIdx.x;
    const int lane = tid & 31, w = tid >> 5;
    const int g = lane >> 2, t4 = lane & 3;

    // ---- stage Q tile (already permuted in gmem): hi->Qhi, lo->Qlo ----
    #pragma unroll
    for (int e = 0; e < 8; e++) {
        int idx = e * 256 + tid;
        int r = idx >> 4, c4 = (idx & 15) * 4;
        float4 qv = *(const float4*)&qh[(size_t)(q0 + r) * DK_ + c4];
        uint4 h, l;
        split3(qv.x, h.x, l.x); split3(qv.y, h.y, l.y);
        split3(qv.z, h.z, l.z); split3(qv.w, h.w, l.w);
        *(uint4*)&Qhi[r * 68 + c4] = h;
        *(uint4*)&Qlo[r * 68 + c4] = l;
    }
    __syncthreads();
    const int r0q = (16 * w + g) * 68, r1q = r0q + 8 * 68;
    uint2 qh02[8], qh13[8];
    #pragma unroll
    for (int dc = 0; dc < 8; dc++) {
        qh02[dc] = *(const uint2*)&Qhi[r0q + dc * 8 + 2 * t4];
        qh13[dc] = *(const uint2*)&Qhi[r1q + dc * 8 + 2 * t4];
    }

    // ---- pass 1: S in 3xTF32, stream w=exp(S) to g_w (perm), accumulate Z ----
    float z0 = 0.f, z1 = 0.f;
    float* wrA = wb + (size_t)(q0 + 16 * w + g) * T_;
    float* wrB = wrA + 8 * T_;
    const int bcol = ((t4 & 1) << 2) + (t4 >> 1);   // perm slot for C cols (2t4,2t4+1)
    for (int kt = 0; kt < T_ / 64; kt++) {
        const int j0 = kt * 64;
        __syncthreads();
        #pragma unroll
        for (int e = 0; e < 4; e++) {
            int idx = e * 256 + tid;
            int r = idx >> 4, c4 = (idx & 15) * 4;
            float4 kv = *(const float4*)&kh[(size_t)(j0 + r) * DK_ + c4];
            uint4 h, l;
            split3(kv.x, h.x, l.x); split3(kv.y, h.y, l.y);
            split3(kv.z, h.z, l.z); split3(kv.w, h.w, l.w);
            *(uint4*)&Kh[r * 68 + c4] = h;
            *(uint4*)&Kl[r * 68 + c4] = l;
        }
        __syncthreads();

        float c[8][4];
        #pragma unroll
        for (int i = 0; i < 8; i++)
            #pragma unroll
            for (int j = 0; j < 4; j++) c[i][j] = 0.f;

        #pragma unroll
        for (int dc = 0; dc < 8; dc++) {
            uint2 ql02 = *(const uint2*)&Qlo[r0q + dc * 8 + 2 * t4];
            uint2 ql13 = *(const uint2*)&Qlo[r1q + dc * 8 + 2 * t4];
            uint2 bhv[8];
            #pragma unroll
            for (int kc = 0; kc < 8; kc++) {
                bhv[kc] = *(const uint2*)&Kh[(kc * 8 + g) * 68 + dc * 8 + 2 * t4];
                mma8(c[kc], qh02[dc].x, qh13[dc].x, qh02[dc].y, qh13[dc].y,
                     bhv[kc].x, bhv[kc].y);                    // hi*hi
            }
            #pragma unroll
            for (int kc = 0; kc < 8; kc++) {
                uint2 blv = *(const uint2*)&Kl[(kc * 8 + g) * 68 + dc * 8 + 2 * t4];
                mma8(c[kc], qh02[dc].x, qh13[dc].x, qh02[dc].y, qh13[dc].y,
                     blv.x, blv.y);                            // hi*lo
            }
            #pragma unroll
            for (int kc = 0; kc < 8; kc++)
                mma8(c[kc], ql02.x, ql13.x, ql02.y, ql13.y,
                     bhv[kc].x, bhv[kc].y);                    // lo*hi
        }

        #pragma unroll
        for (int kc = 0; kc < 8; kc++) {
            float w0 = __expf(c[kc][0]);
            float w1 = __expf(c[kc][1]);
            float w2 = __expf(c[kc][2]);
            float w3 = __expf(c[kc][3]);
            z0 += w0 + w1;
            z1 += w2 + w3;
            const int col = j0 + kc * 8 + bcol;
            wrA[col] = w0; wrA[col + 2] = w1;
            wrB[col] = w2; wrB[col + 2] = w3;
        }
    }
    z0 += __shfl_xor_sync(0xffffffffu, z0, 1);
    z0 += __shfl_xor_sync(0xffffffffu, z0, 2);
    z1 += __shfl_xor_sync(0xffffffffu, z1, 1);
    z1 += __shfl_xor_sync(0xffffffffu, z1, 2);
    const float inv0 = 1.0f / z0, inv1 = 1.0f / z1;
    if (t4 == 0) {
        thr_s[16 * w + g]     = z0 * (1.0f / (float)T_);
        thr_s[16 * w + g + 8] = z1 * (1.0f / (float)T_);
    }

    // ---- pass 2: reload w (permuted), threshold, PV ----
    float o[8][4];
    #pragma unroll
    for (int i = 0; i < 8; i++)
        #pragma unroll
        for (int j = 0; j < 4; j++) o[i][j] = 0.f;

    const int r0p = (16 * w + g) * 68, r1p = r0p + 8 * 68;
    for (int kt = 0; kt < T_ / 64; kt++) {
        const int j0 = kt * 64;
        __syncthreads();
        #pragma unroll
        for (int e = 0; e < 8; e++) {              // P tile: load(perm), thresh, cvt
            int idx = e * 256 + tid;
            int r = idx >> 4, j4 = (idx & 15) * 4;
            float4 w4 = *(const float4*)&wb[(size_t)(q0 + r) * T_ + j0 + j4];
            float th = thr_s[r];
            uint4 p;
            p.x = f2tf(w4.x > th ? w4.x : 0.f);
            p.y = f2tf(w4.y > th ? w4.y : 0.f);
            p.z = f2tf(w4.z > th ? w4.z : 0.f);
            p.w = f2tf(w4.w > th ? w4.w : 0.f);
            *(uint4*)&Ps[r * 68 + j4] = p;
        }
        #pragma unroll
        for (int e = 0; e < 4; e++) {              // V tile 64x64 (standard)
            int idx = e * 256 + tid;
            int r = idx >> 4, d4 = (idx & 15) * 4;
            float4 vv = *(const float4*)&vh[(size_t)(j0 + r) * DK_ + d4];
            *(uint4*)&Vs[r * 68 + d4] = f2tf4(vv);
        }
        __syncthreads();
        #pragma unroll
        for (int kc = 0; kc < 8; kc++) {
            uint2 pa02 = *(const uint2*)&Ps[r0p + kc * 8 + 2 * t4];
            uint2 pa13 = *(const uint2*)&Ps[r1p + kc * 8 + 2 * t4];
            const int vr0 = (kc * 8 + t4) * 68;
            const int vr1 = vr0 + 4 * 68;
            #pragma unroll
            for (int dn = 0; dn < 8; dn++) {
                uint32_t b0 = Vs[vr0 + dn * 8 + g];
                uint32_t b1 = Vs[vr1 + dn * 8 + g];
                mma8(o[dn], pa02.x, pa13.x, pa02.y, pa13.y, b0, b1);
            }
        }
    }

    float* rowA = oh + (size_t)(q0 + 16 * w + g) * DK_;
    float* rowB = rowA + 8 * DK_;
    #pragma unroll
    for (int dn = 0; dn < 8; dn++) {
        int col = dn * 8 + 2 * t4;
        *(float2*)&rowA[col] = make_float2(o[dn][0] * inv0, o[dn][1] * inv0);
        *(float2*)&rowB[col] = make_float2(o[dn][2] * inv1, o[dn][3] * inv1);
    }
}

// ---------------------------------------------------------------------------
// Kernel 3: output projection (single tf32, standard layout).
// ---------------------------------------------------------------------------
__global__ __launch_bounds__(256, 2) void outproj_kernel(
    const float* __restrict__ Wo, const float* __restrict__ bo,
    float* __restrict__ out)
{
    __shared__ uint32_t Xs[128 * 36];
    __shared__ uint32_t Ws[64 * 36];

    const int tid  = threadIdx.x;
    const int lane = tid & 31, w = tid >> 5;
    const int g = lane >> 2, t4 = lane & 3;
    const int m0 = blockIdx.y * 128;
    const int n0 = blockIdx.x * 64;

    float acc[8][4];
    #pragma unroll
    for (int i = 0; i < 8; i++)
        #pragma unroll
        for (int j = 0; j < 4; j++) acc[i][j] = 0.f;

    for (int k0 = 0; k0 < DOUT_; k0 += 32) {
        __syncthreads();
        #pragma unroll
        for (int e = 0; e < 4; e++) {
            int idx = e * 256 + tid;
            int r = idx >> 3, c4 = (idx & 7) * 4;
            int m = m0 + r, bb = m >> 11, t = m & (T_ - 1);
            int kg = k0 + c4, h = kg >> 6, dk = kg & 63;
            int p0 = r * 36 + (c4 & ~7) + ((c4 & 4) >> 2);
            float4 xv = *(const float4*)&g_oh[((size_t)(bb * H_ + h) * T_ + t) * DK_ + dk];
            uint4 xc = f2tf4(xv);
            Xs[p0] = xc.x; Xs[p0+2] = xc.y; Xs[p0+4] = xc.z; Xs[p0+6] = xc.w;
        }
        #pragma unroll
        for (int e = 0; e < 2; e++) {
            int idx = e * 256 + tid;
            int r = idx >> 3, c4 = (idx & 7) * 4;
            int p0 = r * 36 + (c4 & ~7) + ((c4 & 4) >> 2);
            float4 wv = *(const float4*)&Wo[(size_t)(n0 + r) * DOUT_ + k0 + c4];
            uint4 wc = f2tf4(wv);
            Ws[p0] = wc.x; Ws[p0+2] = wc.y; Ws[p0+4] = wc.z; Ws[p0+6] = wc.w;
        }
        __syncthreads();

        uint2 a02[4], a13[4];
        const int r0 = (16 * w + g) * 36, r1 = r0 + 8 * 36;
        #pragma unroll
        for (int kc = 0; kc < 4; kc++) {
            a02[kc] = *(const uint2*)&Xs[r0 + kc * 8 + 2 * t4];
            a13[kc] = *(const uint2*)&Xs[r1 + kc * 8 + 2 * t4];
        }
        #pragma unroll
        for (int kc = 0; kc < 4; kc++) {
            #pragma unroll
            for (int nc = 0; nc < 8; nc++) {
                uint2 bv = *(const uint2*)&Ws[(nc * 8 + g) * 36 + kc * 8 + 2 * t4];
                mma8(acc[nc], a02[kc].x, a13[kc].x, a02[kc].y, a13[kc].y,
                     bv.x, bv.y);
            }
        }
    }

    const int mA = m0 + 16 * w + g;
    float* rowA = out + (size_t)mA * DIN_ + n0;
    float* rowB = rowA + 8 * DIN_;
    #pragma unroll
    for (int nc = 0; nc < 8; nc++) {
        int col = nc * 8 + 2 * t4;
        float bx = bo[n0 + col], by = bo[n0 + col + 1];
        *(float2*)&rowA[col] = make_float2(acc[nc][0] + bx, acc[nc][1] + by);
        *(float2*)&rowB[col] = make_float2(acc[nc][2] + bx, acc[nc][3] + by);
    }
}

// ---------------------------------------------------------------------------
extern "C" void kernel_launch(void* const* d_in, const int* in_sizes, int n_in,
                              void* d_out, int out_size)
{
    const float* q  = (const float*)d_in[0];
    const float* k  = (const float*)d_in[1];
    const float* v  = (const float*)d_in[2];
    const float* Wq = (const float*)d_in[3];
    const float* bq = (const float*)d_in[4];
    const float* Wk = (const float*)d_in[5];
    const float* bk = (const float*)d_in[6];
    const float* Wv = (const float*)d_in[7];
    const float* bv = (const float*)d_in[8];
    const float* Wo = (const float*)d_in[9];
    const float* bo = (const float*)d_in[10];
    float* out = (float*)d_out;

    cudaFuncSetAttribute(proj_kernel,
        cudaFuncAttributeMaxDynamicSharedMemorySize, PROJ_SMEM_BYTES);
    cudaFuncSetAttribute(attn_kernel,
        cudaFuncAttributeMaxDynamicSharedMemorySize, ATTN_SMEM_BYTES);

    proj_kernel<<<dim3(DOUT_ / 64, (B_ * T_) / 128, 3), 256, PROJ_SMEM_BYTES>>>(
        q, k, v, Wq, bq, Wk, bk, Wv, bv);

    attn_kernel<<<dim3(BH_, T_ / 128), 256, ATTN_SMEM_BYTES>>>();

    outproj_kernel<<<dim3(DIN_ / 64, (B_ * T_) / 128), 256>>>(Wo, bo, out);
}

// round 9
// speedup vs baseline: 1.3370x; 1.3370x over previous
#include <cuda_runtime.h>
#include <stdint.h>
#include <math.h>

#define B_    2
#define T_    2048
#define H_    8
#define DK_   64
#define DIN_  512
#define DOUT_ 512
#define BH_   (B_ * H_)

// Scratch (__device__ globals per allocation-free rule)
__device__ float g_qh[BH_ * T_ * DK_];   // [bh][t][dk]
__device__ float g_kh[BH_ * T_ * DK_];
__device__ float g_vh[BH_ * T_ * DK_];
__device__ float g_oh[BH_ * T_ * DK_];   // attention output, head layout
__device__ float g_w[67108864];          // 256 MB [bh][q][k] = exp(scores)

// ---------------------------------------------------------------------------
// helpers
// ---------------------------------------------------------------------------
__device__ __forceinline__ uint32_t f2tf(float f) {
    uint32_t u;
    asm("cvt.rna.tf32.f32 %0, %1;" : "=r"(u) : "f"(f));
    return u;
}
__device__ __forceinline__ uint4 f2tf4(float4 v) {
    uint4 u;
    u.x = f2tf(v.x); u.y = f2tf(v.y); u.z = f2tf(v.z); u.w = f2tf(v.w);
    return u;
}
__device__ __forceinline__ void split3(float x, uint32_t& hi, uint32_t& lo) {
    uint32_t h = f2tf(x);
    hi = h;
    lo = f2tf(x - __uint_as_float(h));
}
// D = A(16x8,row) * B(8x8,col) + D, tf32 operands, f32 accum
__device__ __forceinline__ void mma8(float c[4], const uint32_t a[4],
                                     uint32_t b0, uint32_t b1) {
    asm volatile(
        "mma.sync.aligned.m16n8k8.row.col.f32.tf32.tf32.f32 "
        "{%0,%1,%2,%3},{%4,%5,%6,%7},{%8,%9},{%0,%1,%2,%3};\n"
        : "+f"(c[0]), "+f"(c[1]), "+f"(c[2]), "+f"(c[3])
        : "r"(a[0]), "r"(a[1]), "r"(a[2]), "r"(a[3]), "r"(b0), "r"(b1));
}

#define PROJ_SMEM_BYTES ((128*36*2 + 64*36*2) * 4)       // 55296
#define ATTN_SMEM_BYTES ((256*68 + 128) * 4)             // 70144

// ---------------------------------------------------------------------------
// Kernel 1: fused QKV projection. Q/K 3xTF32, V single tf32.
// Tile 128(M)x64(N), K-step 32, 256 threads. X-tile register prefetch.
// ---------------------------------------------------------------------------
__global__ __launch_bounds__(256, 2) void proj_kernel(
    const float* __restrict__ qx, const float* __restrict__ kx, const float* __restrict__ vx,
    const float* __restrict__ Wq, const float* __restrict__ bq,
    const float* __restrict__ Wk, const float* __restrict__ bk,
    const float* __restrict__ Wv, const float* __restrict__ bv)
{
    extern __shared__ uint32_t smp[];
    uint32_t* Xh = smp;                 // [128][36]
    uint32_t* Xl = Xh + 128 * 36;
    uint32_t* Wh = Xl + 128 * 36;       // [64][36]
    uint32_t* Wl = Wh + 64 * 36;

    const float *x, *W, *bias;
    float* out;
    if (blockIdx.z == 0)      { x = qx; W = Wq; bias = bq; out = g_qh; }
    else if (blockIdx.z == 1) { x = kx; W = Wk; bias = bk; out = g_kh; }
    else                      { x = vx; W = Wv; bias = bv; out = g_vh; }
    const bool precise = (blockIdx.z < 2);

    const int tid  = threadIdx.x;
    const int lane = tid & 31, w = tid >> 5;
    const int g = lane >> 2, t4 = lane & 3;
    const int m0 = blockIdx.y * 128;
    const int n0 = blockIdx.x * 64;

    // per-thread staging coordinates
    const int sr = tid >> 3;              // 0..31
    const int sc4 = (tid & 7) * 4;        // 0..28

    float acc[8][4];
    #pragma unroll
    for (int i = 0; i < 8; i++)
        #pragma unroll
        for (int j = 0; j < 4; j++) acc[i][j] = 0.f;

    // prefetch first X tile (4 x float4)
    float4 xpre[4];
    #pragma unroll
    for (int e = 0; e < 4; e++)
        xpre[e] = *(const float4*)&x[(size_t)(m0 + e * 32 + sr) * DIN_ + sc4];

    for (int k0 = 0; k0 < DIN_; k0 += 32) {
        __syncthreads();
        #pragma unroll
        for (int e = 0; e < 4; e++) {              // X tile 128x32 from prefetch
            int r = e * 32 + sr;
            uint4 h, l;
            split3(xpre[e].x, h.x, l.x); split3(xpre[e].y, h.y, l.y);
            split3(xpre[e].z, h.z, l.z); split3(xpre[e].w, h.w, l.w);
            *(uint4*)&Xh[r * 36 + sc4] = h;
            *(uint4*)&Xl[r * 36 + sc4] = l;
        }
        #pragma unroll
        for (int e = 0; e < 2; e++) {              // W tile 64x32
            int r = e * 32 + sr;
            float4 wv = *(const float4*)&W[(size_t)(n0 + r) * DIN_ + k0 + sc4];
            uint4 h, l;
            split3(wv.x, h.x, l.x); split3(wv.y, h.y, l.y);
            split3(wv.z, h.z, l.z); split3(wv.w, h.w, l.w);
            *(uint4*)&Wh[r * 36 + sc4] = h;
            *(uint4*)&Wl[r * 36 + sc4] = l;
        }
        __syncthreads();

        // prefetch next X tile while mmas run
        if (k0 + 32 < DIN_) {
            #pragma unroll
            for (int e = 0; e < 4; e++)
                xpre[e] = *(const float4*)&x[(size_t)(m0 + e * 32 + sr) * DIN_ + k0 + 32 + sc4];
        }

        uint32_t ah[4][4], al[4][4];
        const int r0 = (16 * w + g) * 36, r1 = r0 + 8 * 36;
        #pragma unroll
        for (int kc = 0; kc < 4; kc++) {
            ah[kc][0] = Xh[r0 + kc * 8 + t4];
            ah[kc][1] = Xh[r1 + kc * 8 + t4];
            ah[kc][2] = Xh[r0 + kc * 8 + t4 + 4];
            ah[kc][3] = Xh[r1 + kc * 8 + t4 + 4];
            al[kc][0] = Xl[r0 + kc * 8 + t4];
            al[kc][1] = Xl[r1 + kc * 8 + t4];
            al[kc][2] = Xl[r0 + kc * 8 + t4 + 4];
            al[kc][3] = Xl[r1 + kc * 8 + t4 + 4];
        }
        #pragma unroll
        for (int kc = 0; kc < 4; kc++) {
            uint32_t bh0[8], bh1[8];
            #pragma unroll
            for (int nc = 0; nc < 8; nc++) {
                const int br = (nc * 8 + g) * 36 + kc * 8;
                bh0[nc] = Wh[br + t4];
                bh1[nc] = Wh[br + t4 + 4];
                mma8(acc[nc], ah[kc], bh0[nc], bh1[nc]);
            }
            if (precise) {
                #pragma unroll
                for (int nc = 0; nc < 8; nc++) {
                    const int br = (nc * 8 + g) * 36 + kc * 8;
                    uint32_t bl0 = Wl[br + t4];
                    uint32_t bl1 = Wl[br + t4 + 4];
                    mma8(acc[nc], ah[kc], bl0, bl1);   // hi*lo
                }
                #pragma unroll
                for (int nc = 0; nc < 8; nc++)
                    mma8(acc[nc], al[kc], bh0[nc], bh1[nc]);   // lo*hi
            }
        }
    }

    const int h = n0 >> 6;
    const int mA = m0 + 16 * w + g;
    const int bA = mA >> 11, tA = mA & (T_ - 1);
    const int mBr = mA + 8;
    const int bB = mBr >> 11, tB = mBr & (T_ - 1);
    float* rowA = out + ((size_t)(bA * H_ + h) * T_ + tA) * DK_;
    float* rowB = out + ((size_t)(bB * H_ + h) * T_ + tB) * DK_;
    #pragma unroll
    for (int nc = 0; nc < 8; nc++) {
        int col = nc * 8 + 2 * t4;
        float bx = bias[n0 + col], by = bias[n0 + col + 1];
        *(float2*)&rowA[col] = make_float2(acc[nc][0] + bx, acc[nc][1] + by);
        *(float2*)&rowB[col] = make_float2(acc[nc][2] + bx, acc[nc][3] + by);
    }
}

// ---------------------------------------------------------------------------
// Kernel 2: attention. Pass 1: QK^T in 3xTF32 (dc-outer, 8 independent
// chains), w=exp(S) -> g_w (streaming stores), Z accumulated; K-tile register
// prefetch. Pass 2: reload w (streaming loads), threshold vs exact fp32 Z/T,
// PV tf32, scale 1/Z; V-tile register prefetch.
// ---------------------------------------------------------------------------
__global__ __launch_bounds__(256, 2) void attn_kernel()
{
    extern __shared__ uint32_t sma[];
    uint32_t* Kh  = sma;                  // [64][68]
    uint32_t* Kl  = Kh + 64 * 68;         // [64][68]
    uint32_t* Qlo = sma + 128 * 68;       // [128][68], persists through pass 1
    uint32_t* Qhi = sma;                  // [128][68] staging (over Kh+Kl)
    uint32_t* Ps  = sma;                  // pass2 [128][68] (over Kh+Kl)
    uint32_t* Vs  = sma + 128 * 68;       // pass2 [64][68]  (over Qlo)
    float*  thr_s = (float*)(sma + 256 * 68);   // [128]

    const int bh = blockIdx.x;
    const int q0 = blockIdx.y * 128;
    const float* qh = g_qh + (size_t)bh * T_ * DK_;
    const float* kh = g_kh + (size_t)bh * T_ * DK_;
    const float* vh = g_vh + (size_t)bh * T_ * DK_;
    float* wb = g_w + (size_t)bh * T_ * T_;
    float* oh = g_oh + (size_t)bh * T_ * DK_;

    const int tid  = threadIdx.x;
    const int lane = tid & 31, w = tid >> 5;
    const int g = lane >> 2, t4 = lane & 3;

    // per-thread staging coordinates (64-row tiles)
    const int sr = tid >> 4;              // 0..15
    const int sc4 = (tid & 15) * 4;       // 0..60

    // ---- stage Q tile: hi -> Qhi scratch, lo -> Qlo (persistent) ----
    #pragma unroll
    for (int e = 0; e < 8; e++) {
        int idx = e * 256 + tid;
        int r = idx >> 4, c4 = (idx & 15) * 4;
        float4 qv = *(const float4*)&qh[(size_t)(q0 + r) * DK_ + c4];
        uint4 h, l;
        split3(qv.x, h.x, l.x); split3(qv.y, h.y, l.y);
        split3(qv.z, h.z, l.z); split3(qv.w, h.w, l.w);
        *(uint4*)&Qhi[r * 68 + c4] = h;
        *(uint4*)&Qlo[r * 68 + c4] = l;
    }
    __syncthreads();
    const int r0q = (16 * w + g) * 68, r1q = r0q + 8 * 68;
    uint32_t qh_[8][4];
    #pragma unroll
    for (int dc = 0; dc < 8; dc++) {
        qh_[dc][0] = Qhi[r0q + dc * 8 + t4];
        qh_[dc][1] = Qhi[r1q + dc * 8 + t4];
        qh_[dc][2] = Qhi[r0q + dc * 8 + t4 + 4];
        qh_[dc][3] = Qhi[r1q + dc * 8 + t4 + 4];
    }

    // ---- pass 1: S in 3xTF32, stream w=exp(S) to g_w, accumulate Z ----
    float z0 = 0.f, z1 = 0.f;
    float* wrA = wb + (size_t)(q0 + 16 * w + g) * T_;
    float* wrB = wrA + 8 * T_;

    // prefetch first K tile (4 x float4)
    float4 kpre[4];
    #pragma unroll
    for (int e = 0; e < 4; e++)
        kpre[e] = *(const float4*)&kh[(size_t)(e * 16 + sr) * DK_ + sc4];

    for (int kt = 0; kt < T_ / 64; kt++) {
        const int j0 = kt * 64;
        __syncthreads();   // q-frag reads / prior c-loop done before K overwrite
        #pragma unroll
        for (int e = 0; e < 4; e++) {
            int r = e * 16 + sr;
            uint4 h, l;
            split3(kpre[e].x, h.x, l.x); split3(kpre[e].y, h.y, l.y);
            split3(kpre[e].z, h.z, l.z); split3(kpre[e].w, h.w, l.w);
            *(uint4*)&Kh[r * 68 + sc4] = h;
            *(uint4*)&Kl[r * 68 + sc4] = l;
        }
        __syncthreads();

        // prefetch next K tile while mmas run
        if (kt + 1 < T_ / 64) {
            #pragma unroll
            for (int e = 0; e < 4; e++)
                kpre[e] = *(const float4*)&kh[(size_t)(j0 + 64 + e * 16 + sr) * DK_ + sc4];
        }

        float c[8][4];
        #pragma unroll
        for (int i = 0; i < 8; i++)
            #pragma unroll
            for (int j = 0; j < 4; j++) c[i][j] = 0.f;

        #pragma unroll
        for (int dc = 0; dc < 8; dc++) {
            uint32_t qlo[4];
            qlo[0] = Qlo[r0q + dc * 8 + t4];
            qlo[1] = Qlo[r1q + dc * 8 + t4];
            qlo[2] = Qlo[r0q + dc * 8 + t4 + 4];
            qlo[3] = Qlo[r1q + dc * 8 + t4 + 4];
            uint32_t bh0[8], bh1[8];
            #pragma unroll
            for (int kc = 0; kc < 8; kc++) {
                const int br = (kc * 8 + g) * 68 + dc * 8;
                bh0[kc] = Kh[br + t4];
                bh1[kc] = Kh[br + t4 + 4];
                mma8(c[kc], qh_[dc], bh0[kc], bh1[kc]);     // hi*hi
            }
            #pragma unroll
            for (int kc = 0; kc < 8; kc++) {
                const int br = (kc * 8 + g) * 68 + dc * 8;
                uint32_t bl0 = Kl[br + t4];
                uint32_t bl1 = Kl[br + t4 + 4];
                mma8(c[kc], qh_[dc], bl0, bl1);             // hi*lo
            }
            #pragma unroll
            for (int kc = 0; kc < 8; kc++)
                mma8(c[kc], qlo, bh0[kc], bh1[kc]);         // lo*hi
        }

        #pragma unroll
        for (int kc = 0; kc < 8; kc++) {
            float w0 = __expf(c[kc][0]);
            float w1 = __expf(c[kc][1]);
            float w2 = __expf(c[kc][2]);
            float w3 = __expf(c[kc][3]);
            z0 += w0 + w1;
            z1 += w2 + w3;
            const int col = j0 + kc * 8 + 2 * t4;
            __stcs((float2*)&wrA[col], make_float2(w0, w1));
            __stcs((float2*)&wrB[col], make_float2(w2, w3));
        }
    }
    z0 += __shfl_xor_sync(0xffffffffu, z0, 1);
    z0 += __shfl_xor_sync(0xffffffffu, z0, 2);
    z1 += __shfl_xor_sync(0xffffffffu, z1, 1);
    z1 += __shfl_xor_sync(0xffffffffu, z1, 2);
    const float inv0 = 1.0f / z0, inv1 = 1.0f / z1;
    if (t4 == 0) {
        thr_s[16 * w + g]     = z0 * (1.0f / (float)T_);
        thr_s[16 * w + g + 8] = z1 * (1.0f / (float)T_);
    }

    // ---- pass 2: reload w, threshold (exact fp32), PV ----
    float o[8][4];
    #pragma unroll
    for (int i = 0; i < 8; i++)
        #pragma unroll
        for (int j = 0; j < 4; j++) o[i][j] = 0.f;

    // prefetch first V tile
    float4 vpre[4];
    #pragma unroll
    for (int e = 0; e < 4; e++)
        vpre[e] = *(const float4*)&vh[(size_t)(e * 16 + sr) * DK_ + sc4];

    const int r0p = (16 * w + g) * 68, r1p = r0p + 8 * 68;
    for (int kt = 0; kt < T_ / 64; kt++) {
        const int j0 = kt * 64;
        __syncthreads();   // orders thr_s writes (first iter) + Ps/Vs reuse
        #pragma unroll
        for (int e = 0; e < 8; e++) {              // P tile 128x64: load, thresh, cvt
            int idx = e * 256 + tid;
            int r = idx >> 4, j4 = (idx & 15) * 4;
            float4 w4 = __ldcs((const float4*)&wb[(size_t)(q0 + r) * T_ + j0 + j4]);
            float th = thr_s[r];
            uint4 p;
            p.x = f2tf(w4.x > th ? w4.x : 0.f);
            p.y = f2tf(w4.y > th ? w4.y : 0.f);
            p.z = f2tf(w4.z > th ? w4.z : 0.f);
            p.w = f2tf(w4.w > th ? w4.w : 0.f);
            *(uint4*)&Ps[r * 68 + j4] = p;
        }
        #pragma unroll
        for (int e = 0; e < 4; e++) {              // V tile 64x64 from prefetch
            int r = e * 16 + sr;
            *(uint4*)&Vs[r * 68 + sc4] = f2tf4(vpre[e]);
        }
        __syncthreads();

        // prefetch next V tile while PV mmas run
        if (kt + 1 < T_ / 64) {
            #pragma unroll
            for (int e = 0; e < 4; e++)
                vpre[e] = *(const float4*)&vh[(size_t)(j0 + 64 + e * 16 + sr) * DK_ + sc4];
        }

        #pragma unroll
        for (int kc = 0; kc < 8; kc++) {
            uint32_t pa[4];
            pa[0] = Ps[r0p + kc * 8 + t4];
            pa[1] = Ps[r1p + kc * 8 + t4];
            pa[2] = Ps[r0p + kc * 8 + t4 + 4];
            pa[3] = Ps[r1p + kc * 8 + t4 + 4];
            const int vr0 = (kc * 8 + t4) * 68;
            const int vr1 = vr0 + 4 * 68;
            #pragma unroll
            for (int dn = 0; dn < 8; dn++) {
                uint32_t b0 = Vs[vr0 + dn * 8 + g];
                uint32_t b1 = Vs[vr1 + dn * 8 + g];
                mma8(o[dn], pa, b0, b1);
            }
        }
    }

    float* rowA = oh + (size_t)(q0 + 16 * w + g) * DK_;
    float* rowB = rowA + 8 * DK_;
    #pragma unroll
    for (int dn = 0; dn < 8; dn++) {
        int col = dn * 8 + 2 * t4;
        *(float2*)&rowA[col] = make_float2(o[dn][0] * inv0, o[dn][1] * inv0);
        *(float2*)&rowB[col] = make_float2(o[dn][2] * inv1, o[dn][3] * inv1);
    }
}

// ---------------------------------------------------------------------------
// Kernel 3: output projection (single tf32). kc-outer for ILP.
// ---------------------------------------------------------------------------
__global__ __launch_bounds__(256, 2) void outproj_kernel(
    const float* __restrict__ Wo, const float* __restrict__ bo,
    float* __restrict__ out)
{
    __shared__ uint32_t Xs[128 * 36];
    __shared__ uint32_t Ws[64 * 36];

    const int tid  = threadIdx.x;
    const int lane = tid & 31, w = tid >> 5;
    const int g = lane >> 2, t4 = lane & 3;
    const int m0 = blockIdx.y * 128;
    const int n0 = blockIdx.x * 64;

    float acc[8][4];
    #pragma unroll
    for (int i = 0; i < 8; i++)
        #pragma unroll
        for (int j = 0; j < 4; j++) acc[i][j] = 0.f;

    for (int k0 = 0; k0 < DOUT_; k0 += 32) {
        __syncthreads();
        #pragma unroll
        for (int e = 0; e < 4; e++) {
            int idx = e * 256 + tid;
            int r = idx >> 3, c4 = (idx & 7) * 4;
            int m = m0 + r, bb = m >> 11, t = m & (T_ - 1);
            int kg = k0 + c4, h = kg >> 6, dk = kg & 63;
            float4 xv = *(const float4*)&g_oh[((size_t)(bb * H_ + h) * T_ + t) * DK_ + dk];
            *(uint4*)&Xs[r * 36 + c4] = f2tf4(xv);
        }
        #pragma unroll
        for (int e = 0; e < 2; e++) {
            int idx = e * 256 + tid;
            int r = idx >> 3, c4 = (idx & 7) * 4;
            float4 wv = *(const float4*)&Wo[(size_t)(n0 + r) * DOUT_ + k0 + c4];
            *(uint4*)&Ws[r * 36 + c4] = f2tf4(wv);
        }
        __syncthreads();

        uint32_t a[4][4];
        const int r0 = (16 * w + g) * 36, r1 = r0 + 8 * 36;
        #pragma unroll
        for (int kc = 0; kc < 4; kc++) {
            a[kc][0] = Xs[r0 + kc * 8 + t4];
            a[kc][1] = Xs[r1 + kc * 8 + t4];
            a[kc][2] = Xs[r0 + kc * 8 + t4 + 4];
            a[kc][3] = Xs[r1 + kc * 8 + t4 + 4];
        }
        #pragma unroll
        for (int kc = 0; kc < 4; kc++) {
            #pragma unroll
            for (int nc = 0; nc < 8; nc++) {
                const int br = (nc * 8 + g) * 36 + kc * 8;
                uint32_t b0 = Ws[br + t4];
                uint32_t b1 = Ws[br + t4 + 4];
                mma8(acc[nc], a[kc], b0, b1);
            }
        }
    }

    const int mA = m0 + 16 * w + g;
    float* rowA = out + (size_t)mA * DIN_ + n0;
    float* rowB = rowA + 8 * DIN_;
    #pragma unroll
    for (int nc = 0; nc < 8; nc++) {
        int col = nc * 8 + 2 * t4;
        float bx = bo[n0 + col], by = bo[n0 + col + 1];
        *(float2*)&rowA[col] = make_float2(acc[nc][0] + bx, acc[nc][1] + by);
        *(float2*)&rowB[col] = make_float2(acc[nc][2] + bx, acc[nc][3] + by);
    }
}

// ---------------------------------------------------------------------------
extern "C" void kernel_launch(void* const* d_in, const int* in_sizes, int n_in,
                              void* d_out, int out_size)
{
    const float* q  = (const float*)d_in[0];
    const float* k  = (const float*)d_in[1];
    const float* v  = (const float*)d_in[2];
    const float* Wq = (const float*)d_in[3];
    const float* bq = (const float*)d_in[4];
    const float* Wk = (const float*)d_in[5];
    const float* bk = (const float*)d_in[6];
    const float* Wv = (const float*)d_in[7];
    const float* bv = (const float*)d_in[8];
    const float* Wo = (const float*)d_in[9];
    const float* bo = (const float*)d_in[10];
    float* out = (float*)d_out;

    cudaFuncSetAttribute(proj_kernel,
        cudaFuncAttributeMaxDynamicSharedMemorySize, PROJ_SMEM_BYTES);
    cudaFuncSetAttribute(attn_kernel,
        cudaFuncAttributeMaxDynamicSharedMemorySize, ATTN_SMEM_BYTES);

    proj_kernel<<<dim3(DOUT_ / 64, (B_ * T_) / 128, 3), 256, PROJ_SMEM_BYTES>>>(
        q, k, v, Wq, bq, Wk, bk, Wv, bv);

    attn_kernel<<<dim3(BH_, T_ / 128), 256, ATTN_SMEM_BYTES>>>();

    outproj_kernel<<<dim3(DIN_ / 64, (B_ * T_) / 128), 256>>>(Wo, bo, out);
}

// round 10
// speedup vs baseline: 1.6134x; 1.2067x over previous
#include <cuda_runtime.h>
#include <cuda_bf16.h>
#include <stdint.h>
#include <math.h>

#define B_    2
#define T_    2048
#define H_    8
#define DK_   64
#define DIN_  512
#define DOUT_ 512
#define BH_   (B_ * H_)

// Scratch (__device__ globals per allocation-free rule)
__device__ float g_qh[BH_ * T_ * DK_];   // [bh][t][dk]
__device__ float g_kh[BH_ * T_ * DK_];
__device__ float g_vh[BH_ * T_ * DK_];
__device__ float g_oh[BH_ * T_ * DK_];   // attention output, head layout
__device__ float g_w[67108864];          // 256 MB [bh][q][k] = exp(scores)

// ---------------------------------------------------------------------------
// helpers
// ---------------------------------------------------------------------------
__device__ __forceinline__ uint32_t f2tf(float f) {
    uint32_t u;
    asm("cvt.rna.tf32.f32 %0, %1;" : "=r"(u) : "f"(f));
    return u;
}
__device__ __forceinline__ uint4 f2tf4(float4 v) {
    uint4 u;
    u.x = f2tf(v.x); u.y = f2tf(v.y); u.z = f2tf(v.z); u.w = f2tf(v.w);
    return u;
}
// split-bf16: x = hi + lo, both bf16; pack two adjacent k-elements per word
// (low 16 bits = even k, high 16 bits = odd k) matching m16n8k16 fragments.
__device__ __forceinline__ void bsplit2x2(float x, float y,
                                          uint32_t& hw, uint32_t& lw) {
    uint16_t xh, yh, xl, yl;
    asm("cvt.rn.bf16.f32 %0, %1;" : "=h"(xh) : "f"(x));
    asm("cvt.rn.bf16.f32 %0, %1;" : "=h"(yh) : "f"(y));
    float xhf = __uint_as_float((uint32_t)xh << 16);
    float yhf = __uint_as_float((uint32_t)yh << 16);
    asm("cvt.rn.bf16.f32 %0, %1;" : "=h"(xl) : "f"(x - xhf));
    asm("cvt.rn.bf16.f32 %0, %1;" : "=h"(yl) : "f"(y - yhf));
    hw = ((uint32_t)yh << 16) | xh;
    lw = ((uint32_t)yl << 16) | xl;
}
// D = A(16x8,row) * B(8x8,col) + D, tf32, f32 accum
__device__ __forceinline__ void mma8(float c[4], const uint32_t a[4],
                                     uint32_t b0, uint32_t b1) {
    asm volatile(
        "mma.sync.aligned.m16n8k8.row.col.f32.tf32.tf32.f32 "
        "{%0,%1,%2,%3},{%4,%5,%6,%7},{%8,%9},{%0,%1,%2,%3};\n"
        : "+f"(c[0]), "+f"(c[1]), "+f"(c[2]), "+f"(c[3])
        : "r"(a[0]), "r"(a[1]), "r"(a[2]), "r"(a[3]), "r"(b0), "r"(b1));
}
// D = A(16x16,row) * B(16x8,col) + D, bf16, f32 accum
__device__ __forceinline__ void mma16(float c[4], const uint32_t a[4],
                                      uint32_t b0, uint32_t b1) {
    asm volatile(
        "mma.sync.aligned.m16n8k16.row.col.f32.bf16.bf16.f32 "
        "{%0,%1,%2,%3},{%4,%5,%6,%7},{%8,%9},{%0,%1,%2,%3};\n"
        : "+f"(c[0]), "+f"(c[1]), "+f"(c[2]), "+f"(c[3])
        : "r"(a[0]), "r"(a[1]), "r"(a[2]), "r"(a[3]), "r"(b0), "r"(b1));
}

#define PROJQK_SMEM_BYTES ((128*20*2 + 64*20*2) * 4)     // 30720
#define PROJV_SMEM_BYTES  ((128*36 + 64*36) * 4)         // 27648
// attn: pass1 Kh[64][36]|Kl[64][36]|Qlo[128][36] (Qhi staging aliases Kh+Kl);
//       pass2 Ps[128][68]|Vs[64][68]; thr after max extent.
#define ATTN_SMEM_BYTES ((13056 + 128) * 4)              // 52736

// ---------------------------------------------------------------------------
// Kernel 1a: Q/K projection, split-bf16 double-double (3 products, k16 mma).
// Tile 128(M)x64(N), K-step 32, 256 threads. X-tile register prefetch.
// ---------------------------------------------------------------------------
__global__ __launch_bounds__(256, 2) void proj_qk_kernel(
    const float* __restrict__ qx, const float* __restrict__ kx,
    const float* __restrict__ Wq, const float* __restrict__ bq,
    const float* __restrict__ Wk, const float* __restrict__ bk)
{
    extern __shared__ uint32_t smp[];
    uint32_t* Xh = smp;                 // [128][20] packed bf16x2 (k pairs)
    uint32_t* Xl = Xh + 128 * 20;
    uint32_t* Wh = Xl + 128 * 20;       // [64][20]
    uint32_t* Wl = Wh + 64 * 20;

    const float *x, *W, *bias;
    float* out;
    if (blockIdx.z == 0) { x = qx; W = Wq; bias = bq; out = g_qh; }
    else                 { x = kx; W = Wk; bias = bk; out = g_kh; }

    const int tid  = threadIdx.x;
    const int lane = tid & 31, w = tid >> 5;
    const int g = lane >> 2, t4 = lane & 3;
    const int m0 = blockIdx.y * 128;
    const int n0 = blockIdx.x * 64;

    const int sr = tid >> 3;              // 0..31
    const int sc4 = (tid & 7) * 4;        // source dim offset
    const int wo  = (tid & 7) * 2;        // packed word offset

    float acc[8][4];
    #pragma unroll
    for (int i = 0; i < 8; i++)
        #pragma unroll
        for (int j = 0; j < 4; j++) acc[i][j] = 0.f;

    float4 xpre[4];
    #pragma unroll
    for (int e = 0; e < 4; e++)
        xpre[e] = *(const float4*)&x[(size_t)(m0 + e * 32 + sr) * DIN_ + sc4];

    for (int k0 = 0; k0 < DIN_; k0 += 32) {
        __syncthreads();
        #pragma unroll
        for (int e = 0; e < 4; e++) {              // X tile 128x32
            int r = e * 32 + sr;
            uint32_t h0, l0, h1, l1;
            bsplit2x2(xpre[e].x, xpre[e].y, h0, l0);
            bsplit2x2(xpre[e].z, xpre[e].w, h1, l1);
            *(uint2*)&Xh[r * 20 + wo] = make_uint2(h0, h1);
            *(uint2*)&Xl[r * 20 + wo] = make_uint2(l0, l1);
        }
        #pragma unroll
        for (int e = 0; e < 2; e++) {              // W tile 64x32
            int r = e * 32 + sr;
            float4 wv = *(const float4*)&W[(size_t)(n0 + r) * DIN_ + k0 + sc4];
            uint32_t h0, l0, h1, l1;
            bsplit2x2(wv.x, wv.y, h0, l0);
            bsplit2x2(wv.z, wv.w, h1, l1);
            *(uint2*)&Wh[r * 20 + wo] = make_uint2(h0, h1);
            *(uint2*)&Wl[r * 20 + wo] = make_uint2(l0, l1);
        }
        __syncthreads();

        if (k0 + 32 < DIN_) {
            #pragma unroll
            for (int e = 0; e < 4; e++)
                xpre[e] = *(const float4*)&x[(size_t)(m0 + e * 32 + sr) * DIN_ + k0 + 32 + sc4];
        }

        uint32_t ah[2][4], al[2][4];
        const int r0 = (16 * w + g) * 20, r1 = r0 + 8 * 20;
        #pragma unroll
        for (int kc = 0; kc < 2; kc++) {
            ah[kc][0] = Xh[r0 + kc * 8 + t4];
            ah[kc][1] = Xh[r1 + kc * 8 + t4];
            ah[kc][2] = Xh[r0 + kc * 8 + t4 + 4];
            ah[kc][3] = Xh[r1 + kc * 8 + t4 + 4];
            al[kc][0] = Xl[r0 + kc * 8 + t4];
            al[kc][1] = Xl[r1 + kc * 8 + t4];
            al[kc][2] = Xl[r0 + kc * 8 + t4 + 4];
            al[kc][3] = Xl[r1 + kc * 8 + t4 + 4];
        }
        #pragma unroll
        for (int kc = 0; kc < 2; kc++) {
            uint32_t bh0[8], bh1[8];
            #pragma unroll
            for (int nc = 0; nc < 8; nc++) {
                const int br = (nc * 8 + g) * 20 + kc * 8;
                bh0[nc] = Wh[br + t4];
                bh1[nc] = Wh[br + t4 + 4];
                mma16(acc[nc], ah[kc], bh0[nc], bh1[nc]);   // hi*hi
            }
            #pragma unroll
            for (int nc = 0; nc < 8; nc++) {
                const int br = (nc * 8 + g) * 20 + kc * 8;
                uint32_t bl0 = Wl[br + t4];
                uint32_t bl1 = Wl[br + t4 + 4];
                mma16(acc[nc], ah[kc], bl0, bl1);           // hi*lo
            }
            #pragma unroll
            for (int nc = 0; nc < 8; nc++)
                mma16(acc[nc], al[kc], bh0[nc], bh1[nc]);   // lo*hi
        }
    }

    const int h = n0 >> 6;
    const int mA = m0 + 16 * w + g;
    const int bA = mA >> 11, tA = mA & (T_ - 1);
    const int mBr = mA + 8;
    const int bB = mBr >> 11, tB = mBr & (T_ - 1);
    float* rowA = out + ((size_t)(bA * H_ + h) * T_ + tA) * DK_;
    float* rowB = out + ((size_t)(bB * H_ + h) * T_ + tB) * DK_;
    #pragma unroll
    for (int nc = 0; nc < 8; nc++) {
        int col = nc * 8 + 2 * t4;
        float bx = bias[n0 + col], by = bias[n0 + col + 1];
        *(float2*)&rowA[col] = make_float2(acc[nc][0] + bx, acc[nc][1] + by);
        *(float2*)&rowB[col] = make_float2(acc[nc][2] + bx, acc[nc][3] + by);
    }
}

// ---------------------------------------------------------------------------
// Kernel 1b: V projection, single tf32. X-tile register prefetch.
// ---------------------------------------------------------------------------
__global__ __launch_bounds__(256, 2) void proj_v_kernel(
    const float* __restrict__ vx,
    const float* __restrict__ Wv, const float* __restrict__ bv)
{
    extern __shared__ uint32_t smv[];
    uint32_t* Xs = smv;                 // [128][36]
    uint32_t* Ws = Xs + 128 * 36;       // [64][36]

    const int tid  = threadIdx.x;
    const int lane = tid & 31, w = tid >> 5;
    const int g = lane >> 2, t4 = lane & 3;
    const int m0 = blockIdx.y * 128;
    const int n0 = blockIdx.x * 64;

    const int sr = tid >> 3;
    const int sc4 = (tid & 7) * 4;

    float acc[8][4];
    #pragma unroll
    for (int i = 0; i < 8; i++)
        #pragma unroll
        for (int j = 0; j < 4; j++) acc[i][j] = 0.f;

    float4 xpre[4];
    #pragma unroll
    for (int e = 0; e < 4; e++)
        xpre[e] = *(const float4*)&vx[(size_t)(m0 + e * 32 + sr) * DIN_ + sc4];

    for (int k0 = 0; k0 < DIN_; k0 += 32) {
        __syncthreads();
        #pragma unroll
        for (int e = 0; e < 4; e++) {
            int r = e * 32 + sr;
            *(uint4*)&Xs[r * 36 + sc4] = f2tf4(xpre[e]);
        }
        #pragma unroll
        for (int e = 0; e < 2; e++) {
            int r = e * 32 + sr;
            float4 wv = *(const float4*)&Wv[(size_t)(n0 + r) * DIN_ + k0 + sc4];
            *(uint4*)&Ws[r * 36 + sc4] = f2tf4(wv);
        }
        __syncthreads();

        if (k0 + 32 < DIN_) {
            #pragma unroll
            for (int e = 0; e < 4; e++)
                xpre[e] = *(const float4*)&vx[(size_t)(m0 + e * 32 + sr) * DIN_ + k0 + 32 + sc4];
        }

        uint32_t a[4][4];
        const int r0 = (16 * w + g) * 36, r1 = r0 + 8 * 36;
        #pragma unroll
        for (int kc = 0; kc < 4; kc++) {
            a[kc][0] = Xs[r0 + kc * 8 + t4];
            a[kc][1] = Xs[r1 + kc * 8 + t4];
            a[kc][2] = Xs[r0 + kc * 8 + t4 + 4];
            a[kc][3] = Xs[r1 + kc * 8 + t4 + 4];
        }
        #pragma unroll
        for (int kc = 0; kc < 4; kc++) {
            #pragma unroll
            for (int nc = 0; nc < 8; nc++) {
                const int br = (nc * 8 + g) * 36 + kc * 8;
                uint32_t b0 = Ws[br + t4];
                uint32_t b1 = Ws[br + t4 + 4];
                mma8(acc[nc], a[kc], b0, b1);
            }
        }
    }

    const int h = n0 >> 6;
    const int mA = m0 + 16 * w + g;
    const int bA = mA >> 11, tA = mA & (T_ - 1);
    const int mBr = mA + 8;
    const int bB = mBr >> 11, tB = mBr & (T_ - 1);
    float* rowA = g_vh + ((size_t)(bA * H_ + h) * T_ + tA) * DK_;
    float* rowB = g_vh + ((size_t)(bB * H_ + h) * T_ + tB) * DK_;
    #pragma unroll
    for (int nc = 0; nc < 8; nc++) {
        int col = nc * 8 + 2 * t4;
        float bx = bv[n0 + col], by = bv[n0 + col + 1];
        *(float2*)&rowA[col] = make_float2(acc[nc][0] + bx, acc[nc][1] + by);
        *(float2*)&rowB[col] = make_float2(acc[nc][2] + bx, acc[nc][3] + by);
    }
}

// ---------------------------------------------------------------------------
// Kernel 2: attention. Pass 1: QK^T split-bf16 (3 products, k16 mma),
// w=exp(S) -> g_w (streaming), Z accumulated; K-tile register prefetch.
// Pass 2: reload w, threshold vs exact fp32 Z/T, PV tf32, scale 1/Z.
// ---------------------------------------------------------------------------
__global__ __launch_bounds__(256, 2) void attn_kernel()
{
    extern __shared__ uint32_t sma[];
    uint32_t* Kh  = sma;                  // [64][36] packed bf16x2
    uint32_t* Kl  = Kh + 64 * 36;         // [64][36]
    uint32_t* Qlo = sma + 128 * 36;       // [128][36], persists pass 1
    uint32_t* Qhi = sma;                  // [128][36] staging (over Kh+Kl)
    uint32_t* Ps  = sma;                  // pass2 [128][68]
    uint32_t* Vs  = sma + 128 * 68;       // pass2 [64][68]
    float*  thr_s = (float*)(sma + 13056);

    const int bh = blockIdx.x;
    const int q0 = blockIdx.y * 128;
    const float* qh = g_qh + (size_t)bh * T_ * DK_;
    const float* kh = g_kh + (size_t)bh * T_ * DK_;
    const float* vh = g_vh + (size_t)bh * T_ * DK_;
    float* wb = g_w + (size_t)bh * T_ * T_;
    float* oh = g_oh + (size_t)bh * T_ * DK_;

    const int tid  = threadIdx.x;
    const int lane = tid & 31, w = tid >> 5;
    const int g = lane >> 2, t4 = lane & 3;

    const int sr = tid >> 4;              // 0..15
    const int sc4 = (tid & 15) * 4;       // dim offset
    const int swo = (tid & 15) * 2;       // packed word offset

    // ---- stage Q tile as split-bf16: hi -> Qhi (scratch), lo -> Qlo ----
    #pragma unroll
    for (int e = 0; e < 8; e++) {
        int idx = e * 256 + tid;
        int r = idx >> 4, c4 = (idx & 15) * 4;
        float4 qv = *(const float4*)&qh[(size_t)(q0 + r) * DK_ + c4];
        uint32_t h0, l0, h1, l1;
        bsplit2x2(qv.x, qv.y, h0, l0);
        bsplit2x2(qv.z, qv.w, h1, l1);
        *(uint2*)&Qhi[r * 36 + (c4 >> 1)] = make_uint2(h0, h1);
        *(uint2*)&Qlo[r * 36 + (c4 >> 1)] = make_uint2(l0, l1);
    }
    __syncthreads();
    const int r0q = (16 * w + g) * 36, r1q = r0q + 8 * 36;
    uint32_t qh_[4][4];
    #pragma unroll
    for (int dc = 0; dc < 4; dc++) {
        qh_[dc][0] = Qhi[r0q + dc * 8 + t4];
        qh_[dc][1] = Qhi[r1q + dc * 8 + t4];
        qh_[dc][2] = Qhi[r0q + dc * 8 + t4 + 4];
        qh_[dc][3] = Qhi[r1q + dc * 8 + t4 + 4];
    }

    // ---- pass 1: S via split-bf16, stream w=exp(S) to g_w, accumulate Z ----
    float z0 = 0.f, z1 = 0.f;
    float* wrA = wb + (size_t)(q0 + 16 * w + g) * T_;
    float* wrB = wrA + 8 * T_;

    float4 kpre[4];
    #pragma unroll
    for (int e = 0; e < 4; e++)
        kpre[e] = *(const float4*)&kh[(size_t)(e * 16 + sr) * DK_ + sc4];

    for (int kt = 0; kt < T_ / 64; kt++) {
        const int j0 = kt * 64;
        __syncthreads();   // frag reads / prior c-loop done before K overwrite
        #pragma unroll
        for (int e = 0; e < 4; e++) {
            int r = e * 16 + sr;
            uint32_t h0, l0, h1, l1;
            bsplit2x2(kpre[e].x, kpre[e].y, h0, l0);
            bsplit2x2(kpre[e].z, kpre[e].w, h1, l1);
            *(uint2*)&Kh[r * 36 + swo] = make_uint2(h0, h1);
            *(uint2*)&Kl[r * 36 + swo] = make_uint2(l0, l1);
        }
        __syncthreads();

        if (kt + 1 < T_ / 64) {
            #pragma unroll
            for (int e = 0; e < 4; e++)
                kpre[e] = *(const float4*)&kh[(size_t)(j0 + 64 + e * 16 + sr) * DK_ + sc4];
        }

        float c[8][4];
        #pragma unroll
        for (int i = 0; i < 8; i++)
            #pragma unroll
            for (int j = 0; j < 4; j++) c[i][j] = 0.f;

        #pragma unroll
        for (int dc = 0; dc < 4; dc++) {
            uint32_t qlo[4];
            qlo[0] = Qlo[r0q + dc * 8 + t4];
            qlo[1] = Qlo[r1q + dc * 8 + t4];
            qlo[2] = Qlo[r0q + dc * 8 + t4 + 4];
            qlo[3] = Qlo[r1q + dc * 8 + t4 + 4];
            uint32_t bh0[8], bh1[8];
            #pragma unroll
            for (int kc = 0; kc < 8; kc++) {
                const int br = (kc * 8 + g) * 36 + dc * 8;
                bh0[kc] = Kh[br + t4];
                bh1[kc] = Kh[br + t4 + 4];
                mma16(c[kc], qh_[dc], bh0[kc], bh1[kc]);    // hi*hi
            }
            #pragma unroll
            for (int kc = 0; kc < 8; kc++) {
                const int br = (kc * 8 + g) * 36 + dc * 8;
                uint32_t bl0 = Kl[br + t4];
                uint32_t bl1 = Kl[br + t4 + 4];
                mma16(c[kc], qh_[dc], bl0, bl1);            // hi*lo
            }
            #pragma unroll
            for (int kc = 0; kc < 8; kc++)
                mma16(c[kc], qlo, bh0[kc], bh1[kc]);        // lo*hi
        }

        #pragma unroll
        for (int kc = 0; kc < 8; kc++) {
            float w0 = __expf(c[kc][0]);
            float w1 = __expf(c[kc][1]);
            float w2 = __expf(c[kc][2]);
            float w3 = __expf(c[kc][3]);
            z0 += w0 + w1;
            z1 += w2 + w3;
            const int col = j0 + kc * 8 + 2 * t4;
            __stcs((float2*)&wrA[col], make_float2(w0, w1));
            __stcs((float2*)&wrB[col], make_float2(w2, w3));
        }
    }
    z0 += __shfl_xor_sync(0xffffffffu, z0, 1);
    z0 += __shfl_xor_sync(0xffffffffu, z0, 2);
    z1 += __shfl_xor_sync(0xffffffffu, z1, 1);
    z1 += __shfl_xor_sync(0xffffffffu, z1, 2);
    const float inv0 = 1.0f / z0, inv1 = 1.0f / z1;
    if (t4 == 0) {
        thr_s[16 * w + g]     = z0 * (1.0f / (float)T_);
        thr_s[16 * w + g + 8] = z1 * (1.0f / (float)T_);
    }

    // ---- pass 2: reload w, threshold (exact fp32), PV in tf32 ----
    float o[8][4];
    #pragma unroll
    for (int i = 0; i < 8; i++)
        #pragma unroll
        for (int j = 0; j < 4; j++) o[i][j] = 0.f;

    float4 vpre[4];
    #pragma unroll
    for (int e = 0; e < 4; e++)
        vpre[e] = *(const float4*)&vh[(size_t)(e * 16 + sr) * DK_ + sc4];

    const int r0p = (16 * w + g) * 68, r1p = r0p + 8 * 68;
    for (int kt = 0; kt < T_ / 64; kt++) {
        const int j0 = kt * 64;
        __syncthreads();   // orders thr_s writes (first iter) + Ps/Vs reuse
        #pragma unroll
        for (int e = 0; e < 8; e++) {              // P tile: load, thresh, cvt
            int idx = e * 256 + tid;
            int r = idx >> 4, j4 = (idx & 15) * 4;
            float4 w4 = __ldcs((const float4*)&wb[(size_t)(q0 + r) * T_ + j0 + j4]);
            float th = thr_s[r];
            uint4 p;
            p.x = f2tf(w4.x > th ? w4.x : 0.f);
            p.y = f2tf(w4.y > th ? w4.y : 0.f);
            p.z = f2tf(w4.z > th ? w4.z : 0.f);
            p.w = f2tf(w4.w > th ? w4.w : 0.f);
            *(uint4*)&Ps[r * 68 + j4] = p;
        }
        #pragma unroll
        for (int e = 0; e < 4; e++) {              // V tile from prefetch
            int r = e * 16 + sr;
            *(uint4*)&Vs[r * 68 + sc4] = f2tf4(vpre[e]);
        }
        __syncthreads();

        if (kt + 1 < T_ / 64) {
            #pragma unroll
            for (int e = 0; e < 4; e++)
                vpre[e] = *(const float4*)&vh[(size_t)(j0 + 64 + e * 16 + sr) * DK_ + sc4];
        }

        #pragma unroll
        for (int kc = 0; kc < 8; kc++) {
            uint32_t pa[4];
            pa[0] = Ps[r0p + kc * 8 + t4];
            pa[1] = Ps[r1p + kc * 8 + t4];
            pa[2] = Ps[r0p + kc * 8 + t4 + 4];
            pa[3] = Ps[r1p + kc * 8 + t4 + 4];
            const int vr0 = (kc * 8 + t4) * 68;
            const int vr1 = vr0 + 4 * 68;
            #pragma unroll
            for (int dn = 0; dn < 8; dn++) {
                uint32_t b0 = Vs[vr0 + dn * 8 + g];
                uint32_t b1 = Vs[vr1 + dn * 8 + g];
                mma8(o[dn], pa, b0, b1);
            }
        }
    }

    float* rowA = oh + (size_t)(q0 + 16 * w + g) * DK_;
    float* rowB = rowA + 8 * DK_;
    #pragma unroll
    for (int dn = 0; dn < 8; dn++) {
        int col = dn * 8 + 2 * t4;
        *(float2*)&rowA[col] = make_float2(o[dn][0] * inv0, o[dn][1] * inv0);
        *(float2*)&rowB[col] = make_float2(o[dn][2] * inv1, o[dn][3] * inv1);
    }
}

// ---------------------------------------------------------------------------
// Kernel 3: output projection (single tf32). kc-outer for ILP.
// ---------------------------------------------------------------------------
__global__ __launch_bounds__(256, 2) void outproj_kernel(
    const float* __restrict__ Wo, const float* __restrict__ bo,
    float* __restrict__ out)
{
    __shared__ uint32_t Xs[128 * 36];
    __shared__ uint32_t Ws[64 * 36];

    const int tid  = threadIdx.x;
    const int lane = tid & 31, w = tid >> 5;
    const int g = lane >> 2, t4 = lane & 3;
    const int m0 = blockIdx.y * 128;
    const int n0 = blockIdx.x * 64;

    float acc[8][4];
    #pragma unroll
    for (int i = 0; i < 8; i++)
        #pragma unroll
        for (int j = 0; j < 4; j++) acc[i][j] = 0.f;

    for (int k0 = 0; k0 < DOUT_; k0 += 32) {
        __syncthreads();
        #pragma unroll
        for (int e = 0; e < 4; e++) {
            int idx = e * 256 + tid;
            int r = idx >> 3, c4 = (idx & 7) * 4;
            int m = m0 + r, bb = m >> 11, t = m & (T_ - 1);
            int kg = k0 + c4, h = kg >> 6, dk = kg & 63;
            float4 xv = *(const float4*)&g_oh[((size_t)(bb * H_ + h) * T_ + t) * DK_ + dk];
            *(uint4*)&Xs[r * 36 + c4] = f2tf4(xv);
        }
        #pragma unroll
        for (int e = 0; e < 2; e++) {
            int idx = e * 256 + tid;
            int r = idx >> 3, c4 = (idx & 7) * 4;
            float4 wv = *(const float4*)&Wo[(size_t)(n0 + r) * DOUT_ + k0 + c4];
            *(uint4*)&Ws[r * 36 + c4] = f2tf4(wv);
        }
        __syncthreads();

        uint32_t a[4][4];
        const int r0 = (16 * w + g) * 36, r1 = r0 + 8 * 36;
        #pragma unroll
        for (int kc = 0; kc < 4; kc++) {
            a[kc][0] = Xs[r0 + kc * 8 + t4];
            a[kc][1] = Xs[r1 + kc * 8 + t4];
            a[kc][2] = Xs[r0 + kc * 8 + t4 + 4];
            a[kc][3] = Xs[r1 + kc * 8 + t4 + 4];
        }
        #pragma unroll
        for (int kc = 0; kc < 4; kc++) {
            #pragma unroll
            for (int nc = 0; nc < 8; nc++) {
                const int br = (nc * 8 + g) * 36 + kc * 8;
                uint32_t b0 = Ws[br + t4];
                uint32_t b1 = Ws[br + t4 + 4];
                mma8(acc[nc], a[kc], b0, b1);
            }
        }
    }

    const int mA = m0 + 16 * w + g;
    float* rowA = out + (size_t)mA * DIN_ + n0;
    float* rowB = rowA + 8 * DIN_;
    #pragma unroll
    for (int nc = 0; nc < 8; nc++) {
        int col = nc * 8 + 2 * t4;
        float bx = bo[n0 + col], by = bo[n0 + col + 1];
        *(float2*)&rowA[col] = make_float2(acc[nc][0] + bx, acc[nc][1] + by);
        *(float2*)&rowB[col] = make_float2(acc[nc][2] + bx, acc[nc][3] + by);
    }
}

// ---------------------------------------------------------------------------
extern "C" void kernel_launch(void* const* d_in, const int* in_sizes, int n_in,
                              void* d_out, int out_size)
{
    const float* q  = (const float*)d_in[0];
    const float* k  = (const float*)d_in[1];
    const float* v  = (const float*)d_in[2];
    const float* Wq = (const float*)d_in[3];
    const float* bq = (const float*)d_in[4];
    const float* Wk = (const float*)d_in[5];
    const float* bk = (const float*)d_in[6];
    const float* Wv = (const float*)d_in[7];
    const float* bv = (const float*)d_in[8];
    const float* Wo = (const float*)d_in[9];
    const float* bo = (const float*)d_in[10];
    float* out = (float*)d_out;

    cudaFuncSetAttribute(attn_kernel,
        cudaFuncAttributeMaxDynamicSharedMemorySize, ATTN_SMEM_BYTES);

    proj_qk_kernel<<<dim3(DOUT_ / 64, (B_ * T_) / 128, 2), 256, PROJQK_SMEM_BYTES>>>(
        q, k, Wq, bq, Wk, bk);
    proj_v_kernel<<<dim3(DOUT_ / 64, (B_ * T_) / 128), 256, PROJV_SMEM_BYTES>>>(
        v, Wv, bv);

    attn_kernel<<<dim3(BH_, T_ / 128), 256, ATTN_SMEM_BYTES>>>();

    outproj_kernel<<<dim3(DIN_ / 64, (B_ * T_) / 128), 256>>>(Wo, bo, out);
}

// round 13
// speedup vs baseline: 1.6246x; 1.0069x over previous
#include <cuda_runtime.h>
#include <cuda_bf16.h>
#include <stdint.h>
#include <math.h>

#define B_    2
#define T_    2048
#define H_    8
#define DK_   64
#define DIN_  512
#define DOUT_ 512
#define BH_   (B_ * H_)

// Scratch (__device__ globals per allocation-free rule)
// Q/K stored pre-split as packed bf16x2 words: word w of a row = head dims
// (2w, 2w+1). hi = bf16(x), lo = bf16(x - hi).
__device__ uint32_t g_qhi[BH_ * T_ * 32];
__device__ uint32_t g_qlo[BH_ * T_ * 32];
__device__ uint32_t g_khi[BH_ * T_ * 32];
__device__ uint32_t g_klo[BH_ * T_ * 32];
__device__ float    g_vh[BH_ * T_ * DK_];
__device__ float    g_oh[BH_ * T_ * DK_];

// ---------------------------------------------------------------------------
// helpers
// ---------------------------------------------------------------------------
__device__ __forceinline__ uint32_t f2tf(float f) {
    uint32_t u;
    asm("cvt.rna.tf32.f32 %0, %1;" : "=r"(u) : "f"(f));
    return u;
}
__device__ __forceinline__ uint4 f2tf4(float4 v) {
    uint4 u;
    u.x = f2tf(v.x); u.y = f2tf(v.y); u.z = f2tf(v.z); u.w = f2tf(v.w);
    return u;
}
// split-bf16: x = hi + lo, both bf16; pack two adjacent k-elements per word.
__device__ __forceinline__ void bsplit2x2(float x, float y,
                                          uint32_t& hw, uint32_t& lw) {
    uint16_t xh, yh, xl, yl;
    asm("cvt.rn.bf16.f32 %0, %1;" : "=h"(xh) : "f"(x));
    asm("cvt.rn.bf16.f32 %0, %1;" : "=h"(yh) : "f"(y));
    float xhf = __uint_as_float((uint32_t)xh << 16);
    float yhf = __uint_as_float((uint32_t)yh << 16);
    asm("cvt.rn.bf16.f32 %0, %1;" : "=h"(xl) : "f"(x - xhf));
    asm("cvt.rn.bf16.f32 %0, %1;" : "=h"(yl) : "f"(y - yhf));
    hw = ((uint32_t)yh << 16) | xh;
    lw = ((uint32_t)yl << 16) | xl;
}
// tf32 k8 mma
__device__ __forceinline__ void mma8(float c[4], const uint32_t a[4],
                                     uint32_t b0, uint32_t b1) {
    asm volatile(
        "mma.sync.aligned.m16n8k8.row.col.f32.tf32.tf32.f32 "
        "{%0,%1,%2,%3},{%4,%5,%6,%7},{%8,%9},{%0,%1,%2,%3};\n"
        : "+f"(c[0]), "+f"(c[1]), "+f"(c[2]), "+f"(c[3])
        : "r"(a[0]), "r"(a[1]), "r"(a[2]), "r"(a[3]), "r"(b0), "r"(b1));
}
// bf16 k16 mma
__device__ __forceinline__ void mma16(float c[4], const uint32_t a[4],
                                      uint32_t b0, uint32_t b1) {
    asm volatile(
        "mma.sync.aligned.m16n8k16.row.col.f32.bf16.bf16.f32 "
        "{%0,%1,%2,%3},{%4,%5,%6,%7},{%8,%9},{%0,%1,%2,%3};\n"
        : "+f"(c[0]), "+f"(c[1]), "+f"(c[2]), "+f"(c[3])
        : "r"(a[0]), "r"(a[1]), "r"(a[2]), "r"(a[3]), "r"(b0), "r"(b1));
}

#define PROJQK_SMEM_BYTES ((128*20*2 + 64*20*2) * 4)     // 30720
#define PROJV_SMEM_BYTES  ((128*36 + 64*36) * 4)         // 27648
// attn smem (words): Kh[64][36]=2304 | Kl 2304 | Qlo[128][36]=4608 |
//                    Vs[64][68]=4352  (Q-hi staging aliases Kh+Kl)
#define ATTN_SMEM_WORDS (2304 + 2304 + 4608 + 4352)
#define ATTN_SMEM_BYTES (ATTN_SMEM_WORDS * 4)            // 54272

// ---------------------------------------------------------------------------
// Kernel 1a: Q/K projection, split-bf16 (3 products, k16 mma).
// Epilogue stores PRE-SPLIT packed hi/lo words for attention.
// ---------------------------------------------------------------------------
__global__ __launch_bounds__(256, 2) void proj_qk_kernel(
    const float* __restrict__ qx, const float* __restrict__ kx,
    const float* __restrict__ Wq, const float* __restrict__ bq,
    const float* __restrict__ Wk, const float* __restrict__ bk)
{
    extern __shared__ uint32_t smp[];
    uint32_t* Xh = smp;
    uint32_t* Xl = Xh + 128 * 20;
    uint32_t* Wh = Xl + 128 * 20;
    uint32_t* Wl = Wh + 64 * 20;

    const float *x, *W, *bias;
    uint32_t *ohi, *olo;
    if (blockIdx.z == 0) { x = qx; W = Wq; bias = bq; ohi = g_qhi; olo = g_qlo; }
    else                 { x = kx; W = Wk; bias = bk; ohi = g_khi; olo = g_klo; }

    const int tid  = threadIdx.x;
    const int lane = tid & 31, w = tid >> 5;
    const int g = lane >> 2, t4 = lane & 3;
    const int m0 = blockIdx.y * 128;
    const int n0 = blockIdx.x * 64;

    const int sr = tid >> 3;
    const int sc4 = (tid & 7) * 4;
    const int wo  = (tid & 7) * 2;

    float acc[8][4];
    #pragma unroll
    for (int i = 0; i < 8; i++)
        #pragma unroll
        for (int j = 0; j < 4; j++) acc[i][j] = 0.f;

    float4 xpre[4];
    #pragma unroll
    for (int e = 0; e < 4; e++)
        xpre[e] = *(const float4*)&x[(size_t)(m0 + e * 32 + sr) * DIN_ + sc4];

    for (int k0 = 0; k0 < DIN_; k0 += 32) {
        __syncthreads();
        #pragma unroll
        for (int e = 0; e < 4; e++) {
            int r = e * 32 + sr;
            uint32_t h0, l0, h1, l1;
            bsplit2x2(xpre[e].x, xpre[e].y, h0, l0);
            bsplit2x2(xpre[e].z, xpre[e].w, h1, l1);
            *(uint2*)&Xh[r * 20 + wo] = make_uint2(h0, h1);
            *(uint2*)&Xl[r * 20 + wo] = make_uint2(l0, l1);
        }
        #pragma unroll
        for (int e = 0; e < 2; e++) {
            int r = e * 32 + sr;
            float4 wv = *(const float4*)&W[(size_t)(n0 + r) * DIN_ + k0 + sc4];
            uint32_t h0, l0, h1, l1;
            bsplit2x2(wv.x, wv.y, h0, l0);
            bsplit2x2(wv.z, wv.w, h1, l1);
            *(uint2*)&Wh[r * 20 + wo] = make_uint2(h0, h1);
            *(uint2*)&Wl[r * 20 + wo] = make_uint2(l0, l1);
        }
        __syncthreads();

        if (k0 + 32 < DIN_) {
            #pragma unroll
            for (int e = 0; e < 4; e++)
                xpre[e] = *(const float4*)&x[(size_t)(m0 + e * 32 + sr) * DIN_ + k0 + 32 + sc4];
        }

        uint32_t ah[2][4], al[2][4];
        const int r0 = (16 * w + g) * 20, r1 = r0 + 8 * 20;
        #pragma unroll
        for (int kc = 0; kc < 2; kc++) {
            ah[kc][0] = Xh[r0 + kc * 8 + t4];
            ah[kc][1] = Xh[r1 + kc * 8 + t4];
            ah[kc][2] = Xh[r0 + kc * 8 + t4 + 4];
            ah[kc][3] = Xh[r1 + kc * 8 + t4 + 4];
            al[kc][0] = Xl[r0 + kc * 8 + t4];
            al[kc][1] = Xl[r1 + kc * 8 + t4];
            al[kc][2] = Xl[r0 + kc * 8 + t4 + 4];
            al[kc][3] = Xl[r1 + kc * 8 + t4 + 4];
        }
        #pragma unroll
        for (int kc = 0; kc < 2; kc++) {
            uint32_t bh0[8], bh1[8];
            #pragma unroll
            for (int nc = 0; nc < 8; nc++) {
                const int br = (nc * 8 + g) * 20 + kc * 8;
                bh0[nc] = Wh[br + t4];
                bh1[nc] = Wh[br + t4 + 4];
                mma16(acc[nc], ah[kc], bh0[nc], bh1[nc]);
            }
            #pragma unroll
            for (int nc = 0; nc < 8; nc++) {
                const int br = (nc * 8 + g) * 20 + kc * 8;
                uint32_t bl0 = Wl[br + t4];
                uint32_t bl1 = Wl[br + t4 + 4];
                mma16(acc[nc], ah[kc], bl0, bl1);
            }
            #pragma unroll
            for (int nc = 0; nc < 8; nc++)
                mma16(acc[nc], al[kc], bh0[nc], bh1[nc]);
        }
    }

    // Epilogue: add bias, split to bf16 hi/lo, store packed words.
    const int h = n0 >> 6;
    const int mA = m0 + 16 * w + g;
    const int bA = mA >> 11, tA = mA & (T_ - 1);
    const int mBr = mA + 8;
    const int bB = mBr >> 11, tB = mBr & (T_ - 1);
    const size_t rowAo = ((size_t)(bA * H_ + h) * T_ + tA) * 32;
    const size_t rowBo = ((size_t)(bB * H_ + h) * T_ + tB) * 32;
    #pragma unroll
    for (int nc = 0; nc < 8; nc++) {
        int col = nc * 8 + 2 * t4;
        int colw = nc * 4 + t4;
        float bx = bias[n0 + col], by = bias[n0 + col + 1];
        uint32_t hw, lw;
        bsplit2x2(acc[nc][0] + bx, acc[nc][1] + by, hw, lw);
        ohi[rowAo + colw] = hw; olo[rowAo + colw] = lw;
        bsplit2x2(acc[nc][2] + bx, acc[nc][3] + by, hw, lw);
        ohi[rowBo + colw] = hw; olo[rowBo + colw] = lw;
    }
}

// ---------------------------------------------------------------------------
// Kernel 1b: V projection, single tf32. (unchanged)
// ---------------------------------------------------------------------------
__global__ __launch_bounds__(256, 2) void proj_v_kernel(
    const float* __restrict__ vx,
    const float* __restrict__ Wv, const float* __restrict__ bv)
{
    extern __shared__ uint32_t smv[];
    uint32_t* Xs = smv;
    uint32_t* Ws = Xs + 128 * 36;

    const int tid  = threadIdx.x;
    const int lane = tid & 31, w = tid >> 5;
    const int g = lane >> 2, t4 = lane & 3;
    const int m0 = blockIdx.y * 128;
    const int n0 = blockIdx.x * 64;

    const int sr = tid >> 3;
    const int sc4 = (tid & 7) * 4;

    float acc[8][4];
    #pragma unroll
    for (int i = 0; i < 8; i++)
        #pragma unroll
        for (int j = 0; j < 4; j++) acc[i][j] = 0.f;

    float4 xpre[4];
    #pragma unroll
    for (int e = 0; e < 4; e++)
        xpre[e] = *(const float4*)&vx[(size_t)(m0 + e * 32 + sr) * DIN_ + sc4];

    for (int k0 = 0; k0 < DIN_; k0 += 32) {
        __syncthreads();
        #pragma unroll
        for (int e = 0; e < 4; e++) {
            int r = e * 32 + sr;
            *(uint4*)&Xs[r * 36 + sc4] = f2tf4(xpre[e]);
        }
        #pragma unroll
        for (int e = 0; e < 2; e++) {
            int r = e * 32 + sr;
            float4 wv = *(const float4*)&Wv[(size_t)(n0 + r) * DIN_ + k0 + sc4];
            *(uint4*)&Ws[r * 36 + sc4] = f2tf4(wv);
        }
        __syncthreads();

        if (k0 + 32 < DIN_) {
            #pragma unroll
            for (int e = 0; e < 4; e++)
                xpre[e] = *(const float4*)&vx[(size_t)(m0 + e * 32 + sr) * DIN_ + k0 + 32 + sc4];
        }

        uint32_t a[4][4];
        const int r0 = (16 * w + g) * 36, r1 = r0 + 8 * 36;
        #pragma unroll
        for (int kc = 0; kc < 4; kc++) {
            a[kc][0] = Xs[r0 + kc * 8 + t4];
            a[kc][1] = Xs[r1 + kc * 8 + t4];
            a[kc][2] = Xs[r0 + kc * 8 + t4 + 4];
            a[kc][3] = Xs[r1 + kc * 8 + t4 + 4];
        }
        #pragma unroll
        for (int kc = 0; kc < 4; kc++) {
            #pragma unroll
            for (int nc = 0; nc < 8; nc++) {
                const int br = (nc * 8 + g) * 36 + kc * 8;
                uint32_t b0 = Ws[br + t4];
                uint32_t b1 = Ws[br + t4 + 4];
                mma8(acc[nc], a[kc], b0, b1);
            }
        }
    }

    const int h = n0 >> 6;
    const int mA = m0 + 16 * w + g;
    const int bA = mA >> 11, tA = mA & (T_ - 1);
    const int mBr = mA + 8;
    const int bB = mBr >> 11, tB = mBr & (T_ - 1);
    float* rowA = g_vh + ((size_t)(bA * H_ + h) * T_ + tA) * DK_;
    float* rowB = g_vh + ((size_t)(bB * H_ + h) * T_ + tB) * DK_;
    #pragma unroll
    for (int nc = 0; nc < 8; nc++) {
        int col = nc * 8 + 2 * t4;
        float bx = bv[n0 + col], by = bv[n0 + col + 1];
        *(float2*)&rowA[col] = make_float2(acc[nc][0] + bx, acc[nc][1] + by);
        *(float2*)&rowB[col] = make_float2(acc[nc][2] + bx, acc[nc][3] + by);
    }
}

// ---------------------------------------------------------------------------
// Kernel 2: attention, recompute architecture (zero score-scratch traffic).
// Pass A: S via split-bf16 k16 mma (dc-outer), Z = sum exp(S). No stores.
// Pass B: recompute S bit-identically, w=exp(S), threshold vs exact fp32 Z/T,
//         shuffle-convert C->A frags, PV in tf32, scale 1/Z.
// ---------------------------------------------------------------------------
__global__ __launch_bounds__(256, 2) void attn_kernel()
{
    extern __shared__ uint32_t sma[];
    uint32_t* Kh  = sma;                  // [64][36]
    uint32_t* Kl  = sma + 2304;           // [64][36]
    uint32_t* Qlo = sma + 4608;           // [128][36], persistent
    uint32_t* Vs  = sma + 9216;           // [64][68], pass B
    uint32_t* Qst = sma;                  // Q-hi staging aliases Kh+Kl

    const int bh = blockIdx.x;
    const int q0 = blockIdx.y * 128;
    const uint32_t* qhiw = g_qhi + (size_t)bh * T_ * 32;
    const uint32_t* qlow = g_qlo + (size_t)bh * T_ * 32;
    const uint32_t* khiw = g_khi + (size_t)bh * T_ * 32;
    const uint32_t* klow = g_klo + (size_t)bh * T_ * 32;
    const float* vh = g_vh + (size_t)bh * T_ * DK_;
    float* oh = g_oh + (size_t)bh * T_ * DK_;

    const int tid  = threadIdx.x;
    const int lane = tid & 31, w = tid >> 5;
    const int g = lane >> 2, t4 = lane & 3;

    // K staging coords (64 rows x 32 words, 2 uint4 per thread per array)
    const int kr  = tid >> 3;             // reused: idx>>3 base
    const int kw8 = (tid & 7) * 4;

    // ---- stage Q (pure copy of pre-split words) ----
    #pragma unroll
    for (int e = 0; e < 4; e++) {
        int idx = e * 256 + tid;
        int r = idx >> 3, w8 = (idx & 7) * 4;
        *(uint4*)&Qst[r * 36 + w8] = *(const uint4*)&qhiw[(size_t)(q0 + r) * 32 + w8];
        *(uint4*)&Qlo[r * 36 + w8] = *(const uint4*)&qlow[(size_t)(q0 + r) * 32 + w8];
    }
    __syncthreads();
    const int r0q = (16 * w + g) * 36, r1q = r0q + 8 * 36;
    uint32_t qh_[4][4];
    #pragma unroll
    for (int dc = 0; dc < 4; dc++) {
        qh_[dc][0] = Qst[r0q + dc * 8 + t4];
        qh_[dc][1] = Qst[r1q + dc * 8 + t4];
        qh_[dc][2] = Qst[r0q + dc * 8 + t4 + 4];
        qh_[dc][3] = Qst[r1q + dc * 8 + t4 + 4];
    }

    // ---- pass A: Z only ----
    float z0 = 0.f, z1 = 0.f;
    uint4 kph[2], kpl[2];
    #pragma unroll
    for (int e = 0; e < 2; e++) {
        int r = (e * 256 + tid) >> 3;
        kph[e] = *(const uint4*)&khiw[(size_t)r * 32 + kw8];
        kpl[e] = *(const uint4*)&klow[(size_t)r * 32 + kw8];
    }

    for (int kt = 0; kt < T_ / 64; kt++) {
        const int j0 = kt * 64;
        __syncthreads();   // frag extraction / prior mma reads done
        #pragma unroll
        for (int e = 0; e < 2; e++) {
            int r = (e * 256 + tid) >> 3;
            *(uint4*)&Kh[r * 36 + kw8] = kph[e];
            *(uint4*)&Kl[r * 36 + kw8] = kpl[e];
        }
        __syncthreads();
        if (kt + 1 < T_ / 64) {
            #pragma unroll
            for (int e = 0; e < 2; e++) {
                int r = (e * 256 + tid) >> 3;
                kph[e] = *(const uint4*)&khiw[(size_t)(j0 + 64 + r) * 32 + kw8];
                kpl[e] = *(const uint4*)&klow[(size_t)(j0 + 64 + r) * 32 + kw8];
            }
        }

        float c[8][4];
        #pragma unroll
        for (int i = 0; i < 8; i++)
            #pragma unroll
            for (int j = 0; j < 4; j++) c[i][j] = 0.f;

        #pragma unroll
        for (int dc = 0; dc < 4; dc++) {
            uint32_t qlo[4];
            qlo[0] = Qlo[r0q + dc * 8 + t4];
            qlo[1] = Qlo[r1q + dc * 8 + t4];
            qlo[2] = Qlo[r0q + dc * 8 + t4 + 4];
            qlo[3] = Qlo[r1q + dc * 8 + t4 + 4];
            uint32_t bh0[8], bh1[8];
            #pragma unroll
            for (int kc = 0; kc < 8; kc++) {
                const int br = (kc * 8 + g) * 36 + dc * 8;
                bh0[kc] = Kh[br + t4];
                bh1[kc] = Kh[br + t4 + 4];
                mma16(c[kc], qh_[dc], bh0[kc], bh1[kc]);    // hi*hi
            }
            #pragma unroll
            for (int kc = 0; kc < 8; kc++) {
                const int br = (kc * 8 + g) * 36 + dc * 8;
                uint32_t bl0 = Kl[br + t4];
                uint32_t bl1 = Kl[br + t4 + 4];
                mma16(c[kc], qh_[dc], bl0, bl1);            // hi*lo
            }
            #pragma unroll
            for (int kc = 0; kc < 8; kc++)
                mma16(c[kc], qlo, bh0[kc], bh1[kc]);        // lo*hi
        }

        #pragma unroll
        for (int kc = 0; kc < 8; kc++) {
            z0 += __expf(c[kc][0]) + __expf(c[kc][1]);
            z1 += __expf(c[kc][2]) + __expf(c[kc][3]);
        }
    }
    z0 += __shfl_xor_sync(0xffffffffu, z0, 1);
    z0 += __shfl_xor_sync(0xffffffffu, z0, 2);
    z1 += __shfl_xor_sync(0xffffffffu, z1, 1);
    z1 += __shfl_xor_sync(0xffffffffu, z1, 2);
    const float thr0 = z0 * (1.0f / (float)T_), inv0 = 1.0f / z0;
    const float thr1 = z1 * (1.0f / (float)T_), inv1 = 1.0f / z1;

    // ---- pass B: recompute S (bit-identical), threshold, PV ----
    float o[8][4];
    #pragma unroll
    for (int i = 0; i < 8; i++)
        #pragma unroll
        for (int j = 0; j < 4; j++) o[i][j] = 0.f;

    const int vsr = tid >> 4;             // 0..15
    const int vsc4 = (tid & 15) * 4;      // 0..60
    float4 vpre[4];
    #pragma unroll
    for (int e = 0; e < 4; e++)
        vpre[e] = *(const float4*)&vh[(size_t)(e * 16 + vsr) * DK_ + vsc4];
    #pragma unroll
    for (int e = 0; e < 2; e++) {
        int r = (e * 256 + tid) >> 3;
        kph[e] = *(const uint4*)&khiw[(size_t)r * 32 + kw8];
        kpl[e] = *(const uint4*)&klow[(size_t)r * 32 + kw8];
    }

    const int srcA = (lane & ~3) | (t4 >> 1);
    const int srcB = srcA + 2;
    const bool odd = (t4 & 1) != 0;

    for (int kt = 0; kt < T_ / 64; kt++) {
        const int j0 = kt * 64;
        __syncthreads();
        #pragma unroll
        for (int e = 0; e < 2; e++) {
            int r = (e * 256 + tid) >> 3;
            *(uint4*)&Kh[r * 36 + kw8] = kph[e];
            *(uint4*)&Kl[r * 36 + kw8] = kpl[e];
        }
        #pragma unroll
        for (int e = 0; e < 4; e++) {
            int r = e * 16 + vsr;
            *(uint4*)&Vs[r * 68 + vsc4] = f2tf4(vpre[e]);
        }
        __syncthreads();
        if (kt + 1 < T_ / 64) {
            #pragma unroll
            for (int e = 0; e < 2; e++) {
                int r = (e * 256 + tid) >> 3;
                kph[e] = *(const uint4*)&khiw[(size_t)(j0 + 64 + r) * 32 + kw8];
                kpl[e] = *(const uint4*)&klow[(size_t)(j0 + 64 + r) * 32 + kw8];
            }
            #pragma unroll
            for (int e = 0; e < 4; e++)
                vpre[e] = *(const float4*)&vh[(size_t)(j0 + 64 + e * 16 + vsr) * DK_ + vsc4];
        }

        // two kc half-sweeps to bound live registers (c[4][4] + o[8][4])
        #pragma unroll
        for (int kcg = 0; kcg < 2; kcg++) {
            float c[4][4];
            #pragma unroll
            for (int i = 0; i < 4; i++)
                #pragma unroll
                for (int j = 0; j < 4; j++) c[i][j] = 0.f;

            #pragma unroll
            for (int dc = 0; dc < 4; dc++) {
                uint32_t qlo[4];
                qlo[0] = Qlo[r0q + dc * 8 + t4];
                qlo[1] = Qlo[r1q + dc * 8 + t4];
                qlo[2] = Qlo[r0q + dc * 8 + t4 + 4];
                qlo[3] = Qlo[r1q + dc * 8 + t4 + 4];
                uint32_t bh0[4], bh1[4];
                #pragma unroll
                for (int k2 = 0; k2 < 4; k2++) {
                    const int br = ((kcg * 4 + k2) * 8 + g) * 36 + dc * 8;
                    bh0[k2] = Kh[br + t4];
                    bh1[k2] = Kh[br + t4 + 4];
                    mma16(c[k2], qh_[dc], bh0[k2], bh1[k2]);    // hi*hi
                }
                #pragma unroll
                for (int k2 = 0; k2 < 4; k2++) {
                    const int br = ((kcg * 4 + k2) * 8 + g) * 36 + dc * 8;
                    uint32_t bl0 = Kl[br + t4];
                    uint32_t bl1 = Kl[br + t4 + 4];
                    mma16(c[k2], qh_[dc], bl0, bl1);            // hi*lo
                }
                #pragma unroll
                for (int k2 = 0; k2 < 4; k2++)
                    mma16(c[k2], qlo, bh0[k2], bh1[k2]);        // lo*hi
            }

            #pragma unroll
            for (int k2 = 0; k2 < 4; k2++) {
                const int kc = kcg * 4 + k2;
                float w0 = __expf(c[k2][0]); w0 = (w0 > thr0) ? w0 : 0.f;
                float w1 = __expf(c[k2][1]); w1 = (w1 > thr0) ? w1 : 0.f;
                float w2 = __expf(c[k2][2]); w2 = (w2 > thr1) ? w2 : 0.f;
                float w3 = __expf(c[k2][3]); w3 = (w3 > thr1) ? w3 : 0.f;

                // C-frag (cols 2t4,2t4+1) -> A-frag (cols t4, t4+4)
                float v00 = __shfl_sync(0xffffffffu, w0, srcA);
                float v01 = __shfl_sync(0xffffffffu, w1, srcA);
                float v20 = __shfl_sync(0xffffffffu, w2, srcA);
                float v21 = __shfl_sync(0xffffffffu, w3, srcA);
                float u00 = __shfl_sync(0xffffffffu, w0, srcB);
                float u01 = __shfl_sync(0xffffffffu, w1, srcB);
                float u20 = __shfl_sync(0xffffffffu, w2, srcB);
                float u21 = __shfl_sync(0xffffffffu, w3, srcB);
                uint32_t pa[4];
                pa[0] = f2tf(odd ? v01 : v00);
                pa[1] = f2tf(odd ? v21 : v20);
                pa[2] = f2tf(odd ? u01 : u00);
                pa[3] = f2tf(odd ? u21 : u20);

                const int vr0 = (kc * 8 + t4) * 68;
                const int vr1 = vr0 + 4 * 68;
                #pragma unroll
                for (int dn = 0; dn < 8; dn++) {
                    uint32_t b0 = Vs[vr0 + dn * 8 + g];
                    uint32_t b1 = Vs[vr1 + dn * 8 + g];
                    mma8(o[dn], pa, b0, b1);
                }
            }
        }
    }

    float* rowA = oh + (size_t)(q0 + 16 * w + g) * DK_;
    float* rowB = rowA + 8 * DK_;
    #pragma unroll
    for (int dn = 0; dn < 8; dn++) {
        int col = dn * 8 + 2 * t4;
        *(float2*)&rowA[col] = make_float2(o[dn][0] * inv0, o[dn][1] * inv0);
        *(float2*)&rowB[col] = make_float2(o[dn][2] * inv1, o[dn][3] * inv1);
    }
}

// ---------------------------------------------------------------------------
// Kernel 3: output projection (single tf32). (unchanged)
// ---------------------------------------------------------------------------
__global__ __launch_bounds__(256, 2) void outproj_kernel(
    const float* __restrict__ Wo, const float* __restrict__ bo,
    float* __restrict__ out)
{
    __shared__ uint32_t Xs[128 * 36];
    __shared__ uint32_t Ws[64 * 36];

    const int tid  = threadIdx.x;
    const int lane = tid & 31, w = tid >> 5;
    const int g = lane >> 2, t4 = lane & 3;
    const int m0 = blockIdx.y * 128;
    const int n0 = blockIdx.x * 64;

    float acc[8][4];
    #pragma unroll
    for (int i = 0; i < 8; i++)
        #pragma unroll
        for (int j = 0; j < 4; j++) acc[i][j] = 0.f;

    for (int k0 = 0; k0 < DOUT_; k0 += 32) {
        __syncthreads();
        #pragma unroll
        for (int e = 0; e < 4; e++) {
            int idx = e * 256 + tid;
            int r = idx >> 3, c4 = (idx & 7) * 4;
            int m = m0 + r, bb = m >> 11, t = m & (T_ - 1);
            int kg = k0 + c4, h = kg >> 6, dk = kg & 63;
            float4 xv = *(const float4*)&g_oh[((size_t)(bb * H_ + h) * T_ + t) * DK_ + dk];
            *(uint4*)&Xs[r * 36 + c4] = f2tf4(xv);
        }
        #pragma unroll
        for (int e = 0; e < 2; e++) {
            int idx = e * 256 + tid;
            int r = idx >> 3, c4 = (idx & 7) * 4;
            float4 wv = *(const float4*)&Wo[(size_t)(n0 + r) * DOUT_ + k0 + c4];
            *(uint4*)&Ws[r * 36 + c4] = f2tf4(wv);
        }
        __syncthreads();

        uint32_t a[4][4];
        const int r0 = (16 * w + g) * 36, r1 = r0 + 8 * 36;
        #pragma unroll
        for (int kc = 0; kc < 4; kc++) {
            a[kc][0] = Xs[r0 + kc * 8 + t4];
            a[kc][1] = Xs[r1 + kc * 8 + t4];
            a[kc][2] = Xs[r0 + kc * 8 + t4 + 4];
            a[kc][3] = Xs[r1 + kc * 8 + t4 + 4];
        }
        #pragma unroll
        for (int kc = 0; kc < 4; kc++) {
            #pragma unroll
            for (int nc = 0; nc < 8; nc++) {
                const int br = (nc * 8 + g) * 36 + kc * 8;
                uint32_t b0 = Ws[br + t4];
                uint32_t b1 = Ws[br + t4 + 4];
                mma8(acc[nc], a[kc], b0, b1);
            }
        }
    }

    const int mA = m0 + 16 * w + g;
    float* rowA = out + (size_t)mA * DIN_ + n0;
    float* rowB = rowA + 8 * DIN_;
    #pragma unroll
    for (int nc = 0; nc < 8; nc++) {
        int col = nc * 8 + 2 * t4;
        float bx = bo[n0 + col], by = bo[n0 + col + 1];
        *(float2*)&rowA[col] = make_float2(acc[nc][0] + bx, acc[nc][1] + by);
        *(float2*)&rowB[col] = make_float2(acc[nc][2] + bx, acc[nc][3] + by);
    }
}

// ---------------------------------------------------------------------------
extern "C" void kernel_launch(void* const* d_in, const int* in_sizes, int n_in,
                              void* d_out, int out_size)
{
    const float* q  = (const float*)d_in[0];
    const float* k  = (const float*)d_in[1];
    const float* v  = (const float*)d_in[2];
    const float* Wq = (const float*)d_in[3];
    const float* bq = (const float*)d_in[4];
    const float* Wk = (const float*)d_in[5];
    const float* bk = (const float*)d_in[6];
    const float* Wv = (const float*)d_in[7];
    const float* bv = (const float*)d_in[8];
    const float* Wo = (const float*)d_in[9];
    const float* bo = (const float*)d_in[10];
    float* out = (float*)d_out;

    cudaFuncSetAttribute(attn_kernel,
        cudaFuncAttributeMaxDynamicSharedMemorySize, ATTN_SMEM_BYTES);

    proj_qk_kernel<<<dim3(DOUT_ / 64, (B_ * T_) / 128, 2), 256, PROJQK_SMEM_BYTES>>>(
        q, k, Wq, bq, Wk, bk);
    proj_v_kernel<<<dim3(DOUT_ / 64, (B_ * T_) / 128), 256, PROJV_SMEM_BYTES>>>(
        v, Wv, bv);

    attn_kernel<<<dim3(BH_, T_ / 128), 256, ATTN_SMEM_BYTES>>>();

    outproj_kernel<<<dim3(DIN_ / 64, (B_ * T_) / 128), 256>>>(Wo, bo, out);
}

// round 16
// speedup vs baseline: 1.6688x; 1.0272x over previous
#include <cuda_runtime.h>
#include <cuda_bf16.h>
#include <stdint.h>
#include <math.h>

#define B_    2
#define T_    2048
#define H_    8
#define DK_   64
#define DIN_  512
#define DOUT_ 512
#define BH_   (B_ * H_)

// Scratch (__device__ globals per allocation-free rule)
// Q/K: pre-split packed bf16x2 words (word w = head dims 2w,2w+1).
// V: tf32 bit patterns. O: tf32 bit patterns (scaled attention output).
__device__ uint32_t g_qhi[BH_ * T_ * 32];
__device__ uint32_t g_qlo[BH_ * T_ * 32];
__device__ uint32_t g_khi[BH_ * T_ * 32];
__device__ uint32_t g_klo[BH_ * T_ * 32];
__device__ uint32_t g_vh[BH_ * T_ * DK_];
__device__ uint32_t g_oh[BH_ * T_ * DK_];

// ---------------------------------------------------------------------------
// helpers
// ---------------------------------------------------------------------------
__device__ __forceinline__ uint32_t f2tf(float f) {
    uint32_t u;
    asm("cvt.rna.tf32.f32 %0, %1;" : "=r"(u) : "f"(f));
    return u;
}
__device__ __forceinline__ uint4 f2tf4(float4 v) {
    uint4 u;
    u.x = f2tf(v.x); u.y = f2tf(v.y); u.z = f2tf(v.z); u.w = f2tf(v.w);
    return u;
}
// split-bf16: x = hi + lo, both bf16; pack two adjacent k-elements per word.
__device__ __forceinline__ void bsplit2x2(float x, float y,
                                          uint32_t& hw, uint32_t& lw) {
    uint16_t xh, yh, xl, yl;
    asm("cvt.rn.bf16.f32 %0, %1;" : "=h"(xh) : "f"(x));
    asm("cvt.rn.bf16.f32 %0, %1;" : "=h"(yh) : "f"(y));
    float xhf = __uint_as_float((uint32_t)xh << 16);
    float yhf = __uint_as_float((uint32_t)yh << 16);
    asm("cvt.rn.bf16.f32 %0, %1;" : "=h"(xl) : "f"(x - xhf));
    asm("cvt.rn.bf16.f32 %0, %1;" : "=h"(yl) : "f"(y - yhf));
    hw = ((uint32_t)yh << 16) | xh;
    lw = ((uint32_t)yl << 16) | xl;
}
// tf32 k8 mma
__device__ __forceinline__ void mma8(float c[4], const uint32_t a[4],
                                     uint32_t b0, uint32_t b1) {
    asm volatile(
        "mma.sync.aligned.m16n8k8.row.col.f32.tf32.tf32.f32 "
        "{%0,%1,%2,%3},{%4,%5,%6,%7},{%8,%9},{%0,%1,%2,%3};\n"
        : "+f"(c[0]), "+f"(c[1]), "+f"(c[2]), "+f"(c[3])
        : "r"(a[0]), "r"(a[1]), "r"(a[2]), "r"(a[3]), "r"(b0), "r"(b1));
}
// bf16 k16 mma
__device__ __forceinline__ void mma16(float c[4], const uint32_t a[4],
                                      uint32_t b0, uint32_t b1) {
    asm volatile(
        "mma.sync.aligned.m16n8k16.row.col.f32.bf16.bf16.f32 "
        "{%0,%1,%2,%3},{%4,%5,%6,%7},{%8,%9},{%0,%1,%2,%3};\n"
        : "+f"(c[0]), "+f"(c[1]), "+f"(c[2]), "+f"(c[3])
        : "r"(a[0]), "r"(a[1]), "r"(a[2]), "r"(a[3]), "r"(b0), "r"(b1));
}

// smem layouts (words), all double-buffered
#define PROJQK_SMEM_WORDS (5120 + 5120 + 2560 + 2560)   // 15360 = 61440 B
#define PROJV_SMEM_WORDS  (9216 + 4608)                 // 13824 = 55296 B
#define OUTPROJ_SMEM_WORDS (9216 + 4608)
// attn: KH2 [2][64][36] @0 | KL2 @4608 | QLO [128][36] @9216 | VS2 [2][64][68] @13824
#define ATTN_SMEM_WORDS 22528                           // 90112 B

// ---------------------------------------------------------------------------
// Kernel 1a: Q/K projection, split-bf16 (3 products, k16 mma), double-buffered.
// Epilogue stores PRE-SPLIT packed hi/lo words for attention.
// ---------------------------------------------------------------------------
__global__ __launch_bounds__(256, 2) void proj_qk_kernel(
    const float* __restrict__ qx, const float* __restrict__ kx,
    const float* __restrict__ Wq, const float* __restrict__ bq,
    const float* __restrict__ Wk, const float* __restrict__ bk)
{
    extern __shared__ uint32_t smp[];

    const float *x, *W, *bias;
    uint32_t *ohi, *olo;
    if (blockIdx.z == 0) { x = qx; W = Wq; bias = bq; ohi = g_qhi; olo = g_qlo; }
    else                 { x = kx; W = Wk; bias = bk; ohi = g_khi; olo = g_klo; }

    const int tid  = threadIdx.x;
    const int lane = tid & 31, w = tid >> 5;
    const int g = lane >> 2, t4 = lane & 3;
    const int m0 = blockIdx.y * 128;
    const int n0 = blockIdx.x * 64;

    const int sr = tid >> 3;              // 0..31
    const int sc4 = (tid & 7) * 4;
    const int wo  = (tid & 7) * 2;

    float acc[8][4];
    #pragma unroll
    for (int i = 0; i < 8; i++)
        #pragma unroll
        for (int j = 0; j < 4; j++) acc[i][j] = 0.f;

    float4 xp[4], wp[2];
    #pragma unroll
    for (int e = 0; e < 4; e++)
        xp[e] = *(const float4*)&x[(size_t)(m0 + e * 32 + sr) * DIN_ + sc4];
    #pragma unroll
    for (int e = 0; e < 2; e++)
        wp[e] = *(const float4*)&W[(size_t)(n0 + e * 32 + sr) * DIN_ + sc4];

    // stage tile 0 into buffer 0
    {
        uint32_t* Xh = smp;
        uint32_t* Xl = smp + 5120;
        uint32_t* Wh = smp + 10240;
        uint32_t* Wl = smp + 12800;
        #pragma unroll
        for (int e = 0; e < 4; e++) {
            int r = e * 32 + sr;
            uint32_t h0, l0, h1, l1;
            bsplit2x2(xp[e].x, xp[e].y, h0, l0);
            bsplit2x2(xp[e].z, xp[e].w, h1, l1);
            *(uint2*)&Xh[r * 20 + wo] = make_uint2(h0, h1);
            *(uint2*)&Xl[r * 20 + wo] = make_uint2(l0, l1);
        }
        #pragma unroll
        for (int e = 0; e < 2; e++) {
            int r = e * 32 + sr;
            uint32_t h0, l0, h1, l1;
            bsplit2x2(wp[e].x, wp[e].y, h0, l0);
            bsplit2x2(wp[e].z, wp[e].w, h1, l1);
            *(uint2*)&Wh[r * 20 + wo] = make_uint2(h0, h1);
            *(uint2*)&Wl[r * 20 + wo] = make_uint2(l0, l1);
        }
    }

    for (int k0 = 0; k0 < DIN_; k0 += 32) {
        const int cb = (k0 >> 5) & 1;
        __syncthreads();

        const bool more = (k0 + 32 < DIN_);
        if (more) {
            #pragma unroll
            for (int e = 0; e < 4; e++)
                xp[e] = *(const float4*)&x[(size_t)(m0 + e * 32 + sr) * DIN_ + k0 + 32 + sc4];
            #pragma unroll
            for (int e = 0; e < 2; e++)
                wp[e] = *(const float4*)&W[(size_t)(n0 + e * 32 + sr) * DIN_ + k0 + 32 + sc4];
        }

        uint32_t* Xh = smp + cb * 2560;
        uint32_t* Xl = smp + 5120 + cb * 2560;
        uint32_t* Wh = smp + 10240 + cb * 1280;
        uint32_t* Wl = smp + 12800 + cb * 1280;

        uint32_t ah[2][4], al[2][4];
        const int r0 = (16 * w + g) * 20, r1 = r0 + 8 * 20;
        #pragma unroll
        for (int kc = 0; kc < 2; kc++) {
            ah[kc][0] = Xh[r0 + kc * 8 + t4];
            ah[kc][1] = Xh[r1 + kc * 8 + t4];
            ah[kc][2] = Xh[r0 + kc * 8 + t4 + 4];
            ah[kc][3] = Xh[r1 + kc * 8 + t4 + 4];
            al[kc][0] = Xl[r0 + kc * 8 + t4];
            al[kc][1] = Xl[r1 + kc * 8 + t4];
            al[kc][2] = Xl[r0 + kc * 8 + t4 + 4];
            al[kc][3] = Xl[r1 + kc * 8 + t4 + 4];
        }
        #pragma unroll
        for (int kc = 0; kc < 2; kc++) {
            uint32_t bh0[8], bh1[8];
            #pragma unroll
            for (int nc = 0; nc < 8; nc++) {
                const int br = (nc * 8 + g) * 20 + kc * 8;
                bh0[nc] = Wh[br + t4];
                bh1[nc] = Wh[br + t4 + 4];
                mma16(acc[nc], ah[kc], bh0[nc], bh1[nc]);
            }
            #pragma unroll
            for (int nc = 0; nc < 8; nc++) {
                const int br = (nc * 8 + g) * 20 + kc * 8;
                uint32_t bl0 = Wl[br + t4];
                uint32_t bl1 = Wl[br + t4 + 4];
                mma16(acc[nc], ah[kc], bl0, bl1);
            }
            #pragma unroll
            for (int nc = 0; nc < 8; nc++)
                mma16(acc[nc], al[kc], bh0[nc], bh1[nc]);
        }

        if (more) {
            uint32_t* Xh2 = smp + (cb ^ 1) * 2560;
            uint32_t* Xl2 = smp + 5120 + (cb ^ 1) * 2560;
            uint32_t* Wh2 = smp + 10240 + (cb ^ 1) * 1280;
            uint32_t* Wl2 = smp + 12800 + (cb ^ 1) * 1280;
            #pragma unroll
            for (int e = 0; e < 4; e++) {
                int r = e * 32 + sr;
                uint32_t h0, l0, h1, l1;
                bsplit2x2(xp[e].x, xp[e].y, h0, l0);
                bsplit2x2(xp[e].z, xp[e].w, h1, l1);
                *(uint2*)&Xh2[r * 20 + wo] = make_uint2(h0, h1);
                *(uint2*)&Xl2[r * 20 + wo] = make_uint2(l0, l1);
            }
            #pragma unroll
            for (int e = 0; e < 2; e++) {
                int r = e * 32 + sr;
                uint32_t h0, l0, h1, l1;
                bsplit2x2(wp[e].x, wp[e].y, h0, l0);
                bsplit2x2(wp[e].z, wp[e].w, h1, l1);
                *(uint2*)&Wh2[r * 20 + wo] = make_uint2(h0, h1);
                *(uint2*)&Wl2[r * 20 + wo] = make_uint2(l0, l1);
            }
        }
    }

    // Epilogue: add bias, split to bf16 hi/lo, store packed words.
    const int h = n0 >> 6;
    const int mA = m0 + 16 * w + g;
    const int bA = mA >> 11, tA = mA & (T_ - 1);
    const int mBr = mA + 8;
    const int bB = mBr >> 11, tB = mBr & (T_ - 1);
    const size_t rowAo = ((size_t)(bA * H_ + h) * T_ + tA) * 32;
    const size_t rowBo = ((size_t)(bB * H_ + h) * T_ + tB) * 32;
    #pragma unroll
    for (int nc = 0; nc < 8; nc++) {
        int col = nc * 8 + 2 * t4;
        int colw = nc * 4 + t4;
        float bx = bias[n0 + col], by = bias[n0 + col + 1];
        uint32_t hw, lw;
        bsplit2x2(acc[nc][0] + bx, acc[nc][1] + by, hw, lw);
        ohi[rowAo + colw] = hw; olo[rowAo + colw] = lw;
        bsplit2x2(acc[nc][2] + bx, acc[nc][3] + by, hw, lw);
        ohi[rowBo + colw] = hw; olo[rowBo + colw] = lw;
    }
}

// ---------------------------------------------------------------------------
// Kernel 1b: V projection, single tf32, double-buffered.
// Epilogue stores TF32 bit patterns (attention uses them directly).
// ---------------------------------------------------------------------------
__global__ __launch_bounds__(256, 2) void proj_v_kernel(
    const float* __restrict__ vx,
    const float* __restrict__ Wv, const float* __restrict__ bv)
{
    extern __shared__ uint32_t smv[];

    const int tid  = threadIdx.x;
    const int lane = tid & 31, w = tid >> 5;
    const int g = lane >> 2, t4 = lane & 3;
    const int m0 = blockIdx.y * 128;
    const int n0 = blockIdx.x * 64;

    const int sr = tid >> 3;
    const int sc4 = (tid & 7) * 4;

    float acc[8][4];
    #pragma unroll
    for (int i = 0; i < 8; i++)
        #pragma unroll
        for (int j = 0; j < 4; j++) acc[i][j] = 0.f;

    float4 xp[4], wp[2];
    #pragma unroll
    for (int e = 0; e < 4; e++)
        xp[e] = *(const float4*)&vx[(size_t)(m0 + e * 32 + sr) * DIN_ + sc4];
    #pragma unroll
    for (int e = 0; e < 2; e++)
        wp[e] = *(const float4*)&Wv[(size_t)(n0 + e * 32 + sr) * DIN_ + sc4];

    {
        uint32_t* Xs = smv;
        uint32_t* Ws = smv + 9216;
        #pragma unroll
        for (int e = 0; e < 4; e++)
            *(uint4*)&Xs[(e * 32 + sr) * 36 + sc4] = f2tf4(xp[e]);
        #pragma unroll
        for (int e = 0; e < 2; e++)
            *(uint4*)&Ws[(e * 32 + sr) * 36 + sc4] = f2tf4(wp[e]);
    }

    for (int k0 = 0; k0 < DIN_; k0 += 32) {
        const int cb = (k0 >> 5) & 1;
        __syncthreads();
        const bool more = (k0 + 32 < DIN_);
        if (more) {
            #pragma unroll
            for (int e = 0; e < 4; e++)
                xp[e] = *(const float4*)&vx[(size_t)(m0 + e * 32 + sr) * DIN_ + k0 + 32 + sc4];
            #pragma unroll
            for (int e = 0; e < 2; e++)
                wp[e] = *(const float4*)&Wv[(size_t)(n0 + e * 32 + sr) * DIN_ + k0 + 32 + sc4];
        }

        uint32_t* Xs = smv + cb * 4608;
        uint32_t* Ws = smv + 9216 + cb * 2304;

        uint32_t a[4][4];
        const int r0 = (16 * w + g) * 36, r1 = r0 + 8 * 36;
        #pragma unroll
        for (int kc = 0; kc < 4; kc++) {
            a[kc][0] = Xs[r0 + kc * 8 + t4];
            a[kc][1] = Xs[r1 + kc * 8 + t4];
            a[kc][2] = Xs[r0 + kc * 8 + t4 + 4];
            a[kc][3] = Xs[r1 + kc * 8 + t4 + 4];
        }
        #pragma unroll
        for (int kc = 0; kc < 4; kc++) {
            #pragma unroll
            for (int nc = 0; nc < 8; nc++) {
                const int br = (nc * 8 + g) * 36 + kc * 8;
                uint32_t b0 = Ws[br + t4];
                uint32_t b1 = Ws[br + t4 + 4];
                mma8(acc[nc], a[kc], b0, b1);
            }
        }

        if (more) {
            uint32_t* Xs2 = smv + (cb ^ 1) * 4608;
            uint32_t* Ws2 = smv + 9216 + (cb ^ 1) * 2304;
            #pragma unroll
            for (int e = 0; e < 4; e++)
                *(uint4*)&Xs2[(e * 32 + sr) * 36 + sc4] = f2tf4(xp[e]);
            #pragma unroll
            for (int e = 0; e < 2; e++)
                *(uint4*)&Ws2[(e * 32 + sr) * 36 + sc4] = f2tf4(wp[e]);
        }
    }

    const int h = n0 >> 6;
    const int mA = m0 + 16 * w + g;
    const int bA = mA >> 11, tA = mA & (T_ - 1);
    const int mBr = mA + 8;
    const int bB = mBr >> 11, tB = mBr & (T_ - 1);
    uint32_t* rowA = g_vh + ((size_t)(bA * H_ + h) * T_ + tA) * DK_;
    uint32_t* rowB = g_vh + ((size_t)(bB * H_ + h) * T_ + tB) * DK_;
    #pragma unroll
    for (int nc = 0; nc < 8; nc++) {
        int col = nc * 8 + 2 * t4;
        float bx = bv[n0 + col], by = bv[n0 + col + 1];
        rowA[col]     = f2tf(acc[nc][0] + bx);
        rowA[col + 1] = f2tf(acc[nc][1] + by);
        rowB[col]     = f2tf(acc[nc][2] + bx);
        rowB[col + 1] = f2tf(acc[nc][3] + by);
    }
}

// ---------------------------------------------------------------------------
// Kernel 2: attention, recompute architecture, double-buffered K/V tiles.
// Pass A: S via split-bf16 k16 mma (dc-outer), Z = sum exp(S). No stores.
// Pass B: recompute S bit-identically, threshold vs exact fp32 Z/T,
//         shuffle-convert C->A frags, PV in tf32, output tf32 bits * 1/Z.
// ---------------------------------------------------------------------------
__global__ __launch_bounds__(256, 2) void attn_kernel()
{
    extern __shared__ uint32_t sma[];
    // KH2 @0 (2x2304) | KL2 @4608 | QLO @9216 (4608) | VS2 @13824 (2x4352)
    uint32_t* Qlo = sma + 9216;
    uint32_t* Qst = sma;                  // Q-hi staging aliases KH2

    const int bh = blockIdx.x;
    const int q0 = blockIdx.y * 128;
    const uint32_t* qhiw = g_qhi + (size_t)bh * T_ * 32;
    const uint32_t* qlow = g_qlo + (size_t)bh * T_ * 32;
    const uint32_t* khiw = g_khi + (size_t)bh * T_ * 32;
    const uint32_t* klow = g_klo + (size_t)bh * T_ * 32;
    const uint32_t* vh = g_vh + (size_t)bh * T_ * DK_;
    uint32_t* oh = g_oh + (size_t)bh * T_ * DK_;

    const int tid  = threadIdx.x;
    const int lane = tid & 31, w = tid >> 5;
    const int g = lane >> 2, t4 = lane & 3;
    const int kw8 = (tid & 7) * 4;

    // ---- stage Q (pure copy of pre-split words) ----
    #pragma unroll
    for (int e = 0; e < 4; e++) {
        int idx = e * 256 + tid;
        int r = idx >> 3, w8 = (idx & 7) * 4;
        *(uint4*)&Qst[r * 36 + w8] = *(const uint4*)&qhiw[(size_t)(q0 + r) * 32 + w8];
        *(uint4*)&Qlo[r * 36 + w8] = *(const uint4*)&qlow[(size_t)(q0 + r) * 32 + w8];
    }
    __syncthreads();
    const int r0q = (16 * w + g) * 36, r1q = r0q + 8 * 36;
    uint32_t qh_[4][4];
    #pragma unroll
    for (int dc = 0; dc < 4; dc++) {
        qh_[dc][0] = Qst[r0q + dc * 8 + t4];
        qh_[dc][1] = Qst[r1q + dc * 8 + t4];
        qh_[dc][2] = Qst[r0q + dc * 8 + t4 + 4];
        qh_[dc][3] = Qst[r1q + dc * 8 + t4 + 4];
    }
    __syncthreads();   // all frags extracted before K overwrites Q-hi staging

    // ---- pass A: Z only ----
    float z0 = 0.f, z1 = 0.f;
    uint4 kph[2], kpl[2];
    #pragma unroll
    for (int e = 0; e < 2; e++) {
        int r = (e * 256 + tid) >> 3;
        kph[e] = *(const uint4*)&khiw[(size_t)r * 32 + kw8];
        kpl[e] = *(const uint4*)&klow[(size_t)r * 32 + kw8];
    }
    // stage K tile 0 -> buffer 0
    #pragma unroll
    for (int e = 0; e < 2; e++) {
        int r = (e * 256 + tid) >> 3;
        *(uint4*)&sma[r * 36 + kw8]        = kph[e];
        *(uint4*)&sma[4608 + r * 36 + kw8] = kpl[e];
    }

    for (int kt = 0; kt < T_ / 64; kt++) {
        const int j0 = kt * 64;
        const int cb = kt & 1;
        __syncthreads();
        const bool more = (kt + 1 < T_ / 64);
        if (more) {
            #pragma unroll
            for (int e = 0; e < 2; e++) {
                int r = (e * 256 + tid) >> 3;
                kph[e] = *(const uint4*)&khiw[(size_t)(j0 + 64 + r) * 32 + kw8];
                kpl[e] = *(const uint4*)&klow[(size_t)(j0 + 64 + r) * 32 + kw8];
            }
        }
        uint32_t* Kh = sma + cb * 2304;
        uint32_t* Kl = sma + 4608 + cb * 2304;

        float c[8][4];
        #pragma unroll
        for (int i = 0; i < 8; i++)
            #pragma unroll
            for (int j = 0; j < 4; j++) c[i][j] = 0.f;

        #pragma unroll
        for (int dc = 0; dc < 4; dc++) {
            uint32_t qlo[4];
            qlo[0] = Qlo[r0q + dc * 8 + t4];
            qlo[1] = Qlo[r1q + dc * 8 + t4];
            qlo[2] = Qlo[r0q + dc * 8 + t4 + 4];
            qlo[3] = Qlo[r1q + dc * 8 + t4 + 4];
            uint32_t bh0[8], bh1[8];
            #pragma unroll
            for (int kc = 0; kc < 8; kc++) {
                const int br = (kc * 8 + g) * 36 + dc * 8;
                bh0[kc] = Kh[br + t4];
                bh1[kc] = Kh[br + t4 + 4];
                mma16(c[kc], qh_[dc], bh0[kc], bh1[kc]);    // hi*hi
            }
            #pragma unroll
            for (int kc = 0; kc < 8; kc++) {
                const int br = (kc * 8 + g) * 36 + dc * 8;
                uint32_t bl0 = Kl[br + t4];
                uint32_t bl1 = Kl[br + t4 + 4];
                mma16(c[kc], qh_[dc], bl0, bl1);            // hi*lo
            }
            #pragma unroll
            for (int kc = 0; kc < 8; kc++)
                mma16(c[kc], qlo, bh0[kc], bh1[kc]);        // lo*hi
        }

        #pragma unroll
        for (int kc = 0; kc < 8; kc++) {
            z0 += __expf(c[kc][0]) + __expf(c[kc][1]);
            z1 += __expf(c[kc][2]) + __expf(c[kc][3]);
        }

        if (more) {
            uint32_t* Kh2 = sma + (cb ^ 1) * 2304;
            uint32_t* Kl2 = sma + 4608 + (cb ^ 1) * 2304;
            #pragma unroll
            for (int e = 0; e < 2; e++) {
                int r = (e * 256 + tid) >> 3;
                *(uint4*)&Kh2[r * 36 + kw8] = kph[e];
                *(uint4*)&Kl2[r * 36 + kw8] = kpl[e];
            }
        }
    }
    z0 += __shfl_xor_sync(0xffffffffu, z0, 1);
    z0 += __shfl_xor_sync(0xffffffffu, z0, 2);
    z1 += __shfl_xor_sync(0xffffffffu, z1, 1);
    z1 += __shfl_xor_sync(0xffffffffu, z1, 2);
    const float thr0 = z0 * (1.0f / (float)T_), inv0 = 1.0f / z0;
    const float thr1 = z1 * (1.0f / (float)T_), inv1 = 1.0f / z1;

    // ---- pass B: recompute S (bit-identical), threshold, PV ----
    float o[8][4];
    #pragma unroll
    for (int i = 0; i < 8; i++)
        #pragma unroll
        for (int j = 0; j < 4; j++) o[i][j] = 0.f;

    const int vsr = tid >> 4;             // 0..15
    const int vsc4 = (tid & 15) * 4;      // 0..60
    uint4 vp[4];
    #pragma unroll
    for (int e = 0; e < 4; e++)
        vp[e] = *(const uint4*)&vh[(size_t)(e * 16 + vsr) * DK_ + vsc4];
    #pragma unroll
    for (int e = 0; e < 2; e++) {
        int r = (e * 256 + tid) >> 3;
        kph[e] = *(const uint4*)&khiw[(size_t)r * 32 + kw8];
        kpl[e] = *(const uint4*)&klow[(size_t)r * 32 + kw8];
    }
    __syncthreads();   // pass-A reads of K buffers complete everywhere
    // stage tile 0 -> buffer 0 (K + V)
    #pragma unroll
    for (int e = 0; e < 2; e++) {
        int r = (e * 256 + tid) >> 3;
        *(uint4*)&sma[r * 36 + kw8]        = kph[e];
        *(uint4*)&sma[4608 + r * 36 + kw8] = kpl[e];
    }
    #pragma unroll
    for (int e = 0; e < 4; e++)
        *(uint4*)&sma[13824 + (e * 16 + vsr) * 68 + vsc4] = vp[e];

    const int srcA = (lane & ~3) | (t4 >> 1);
    const int srcB = srcA + 2;
    const bool odd = (t4 & 1) != 0;

    for (int kt = 0; kt < T_ / 64; kt++) {
        const int j0 = kt * 64;
        const int cb = kt & 1;
        __syncthreads();
        const bool more = (kt + 1 < T_ / 64);
        if (more) {
            #pragma unroll
            for (int e = 0; e < 2; e++) {
                int r = (e * 256 + tid) >> 3;
                kph[e] = *(const uint4*)&khiw[(size_t)(j0 + 64 + r) * 32 + kw8];
                kpl[e] = *(const uint4*)&klow[(size_t)(j0 + 64 + r) * 32 + kw8];
            }
            #pragma unroll
            for (int e = 0; e < 4; e++)
                vp[e] = *(const uint4*)&vh[(size_t)(j0 + 64 + e * 16 + vsr) * DK_ + vsc4];
        }
        uint32_t* Kh = sma + cb * 2304;
        uint32_t* Kl = sma + 4608 + cb * 2304;
        uint32_t* Vs = sma + 13824 + cb * 4352;

        // two kc half-sweeps to bound live registers
        #pragma unroll
        for (int kcg = 0; kcg < 2; kcg++) {
            float c[4][4];
            #pragma unroll
            for (int i = 0; i < 4; i++)
                #pragma unroll
                for (int j = 0; j < 4; j++) c[i][j] = 0.f;

            #pragma unroll
            for (int dc = 0; dc < 4; dc++) {
                uint32_t qlo[4];
                qlo[0] = Qlo[r0q + dc * 8 + t4];
                qlo[1] = Qlo[r1q + dc * 8 + t4];
                qlo[2] = Qlo[r0q + dc * 8 + t4 + 4];
                qlo[3] = Qlo[r1q + dc * 8 + t4 + 4];
                uint32_t bh0[4], bh1[4];
                #pragma unroll
                for (int k2 = 0; k2 < 4; k2++) {
                    const int br = ((kcg * 4 + k2) * 8 + g) * 36 + dc * 8;
                    bh0[k2] = Kh[br + t4];
                    bh1[k2] = Kh[br + t4 + 4];
                    mma16(c[k2], qh_[dc], bh0[k2], bh1[k2]);    // hi*hi
                }
                #pragma unroll
                for (int k2 = 0; k2 < 4; k2++) {
                    const int br = ((kcg * 4 + k2) * 8 + g) * 36 + dc * 8;
                    uint32_t bl0 = Kl[br + t4];
                    uint32_t bl1 = Kl[br + t4 + 4];
                    mma16(c[k2], qh_[dc], bl0, bl1);            // hi*lo
                }
                #pragma unroll
                for (int k2 = 0; k2 < 4; k2++)
                    mma16(c[k2], qlo, bh0[k2], bh1[k2]);        // lo*hi
            }

            #pragma unroll
            for (int k2 = 0; k2 < 4; k2++) {
                const int kc = kcg * 4 + k2;
                float w0 = __expf(c[k2][0]); w0 = (w0 > thr0) ? w0 : 0.f;
                float w1 = __expf(c[k2][1]); w1 = (w1 > thr0) ? w1 : 0.f;
                float w2 = __expf(c[k2][2]); w2 = (w2 > thr1) ? w2 : 0.f;
                float w3 = __expf(c[k2][3]); w3 = (w3 > thr1) ? w3 : 0.f;

                // C-frag (cols 2t4,2t4+1) -> A-frag (cols t4, t4+4)
                float v00 = __shfl_sync(0xffffffffu, w0, srcA);
                float v01 = __shfl_sync(0xffffffffu, w1, srcA);
                float v20 = __shfl_sync(0xffffffffu, w2, srcA);
                float v21 = __shfl_sync(0xffffffffu, w3, srcA);
                float u00 = __shfl_sync(0xffffffffu, w0, srcB);
                float u01 = __shfl_sync(0xffffffffu, w1, srcB);
                float u20 = __shfl_sync(0xffffffffu, w2, srcB);
                float u21 = __shfl_sync(0xffffffffu, w3, srcB);
                uint32_t pa[4];
                pa[0] = f2tf(odd ? v01 : v00);
                pa[1] = f2tf(odd ? v21 : v20);
                pa[2] = f2tf(odd ? u01 : u00);
                pa[3] = f2tf(odd ? u21 : u20);

                const int vr0 = (kc * 8 + t4) * 68;
                const int vr1 = vr0 + 4 * 68;
                #pragma unroll
                for (int dn = 0; dn < 8; dn++) {
                    uint32_t b0 = Vs[vr0 + dn * 8 + g];
                    uint32_t b1 = Vs[vr1 + dn * 8 + g];
                    mma8(o[dn], pa, b0, b1);
                }
            }
        }

        if (more) {
            uint32_t* Kh2 = sma + (cb ^ 1) * 2304;
            uint32_t* Kl2 = sma + 4608 + (cb ^ 1) * 2304;
            uint32_t* Vs2 = sma + 13824 + (cb ^ 1) * 4352;
            #pragma unroll
            for (int e = 0; e < 2; e++) {
                int r = (e * 256 + tid) >> 3;
                *(uint4*)&Kh2[r * 36 + kw8] = kph[e];
                *(uint4*)&Kl2[r * 36 + kw8] = kpl[e];
            }
            #pragma unroll
            for (int e = 0; e < 4; e++)
                *(uint4*)&Vs2[(e * 16 + vsr) * 68 + vsc4] = vp[e];
        }
    }

    // epilogue: scale by 1/Z, store TF32 bits (outproj consumes directly)
    uint32_t* rowA = oh + (size_t)(q0 + 16 * w + g) * DK_;
    uint32_t* rowB = rowA + 8 * DK_;
    #pragma unroll
    for (int dn = 0; dn < 8; dn++) {
        int col = dn * 8 + 2 * t4;
        rowA[col]     = f2tf(o[dn][0] * inv0);
        rowA[col + 1] = f2tf(o[dn][1] * inv0);
        rowB[col]     = f2tf(o[dn][2] * inv1);
        rowB[col + 1] = f2tf(o[dn][3] * inv1);
    }
}

// ---------------------------------------------------------------------------
// Kernel 3: output projection (single tf32), double-buffered.
// A-tile staging is a pure copy (g_oh already holds tf32 bits).
// ---------------------------------------------------------------------------
__global__ __launch_bounds__(256, 2) void outproj_kernel(
    const float* __restrict__ Wo, const float* __restrict__ bo,
    float* __restrict__ out)
{
    extern __shared__ uint32_t smo[];

    const int tid  = threadIdx.x;
    const int lane = tid & 31, w = tid >> 5;
    const int g = lane >> 2, t4 = lane & 3;
    const int m0 = blockIdx.y * 128;
    const int n0 = blockIdx.x * 64;

    const int sr = tid >> 3;
    const int sc4 = (tid & 7) * 4;

    float acc[8][4];
    #pragma unroll
    for (int i = 0; i < 8; i++)
        #pragma unroll
        for (int j = 0; j < 4; j++) acc[i][j] = 0.f;

    auto xaddr = [&](int k0, int e) -> const uint4* {
        int r = e * 32 + sr;
        int m = m0 + r, bb = m >> 11, t = m & (T_ - 1);
        int kg = k0 + sc4, h = kg >> 6, dk = kg & 63;
        return (const uint4*)&g_oh[((size_t)(bb * H_ + h) * T_ + t) * DK_ + dk];
    };

    uint4 xp[4];
    float4 wp[2];
    #pragma unroll
    for (int e = 0; e < 4; e++) xp[e] = *xaddr(0, e);
    #pragma unroll
    for (int e = 0; e < 2; e++)
        wp[e] = *(const float4*)&Wo[(size_t)(n0 + e * 32 + sr) * DOUT_ + sc4];

    {
        uint32_t* Xs = smo;
        uint32_t* Ws = smo + 9216;
        #pragma unroll
        for (int e = 0; e < 4; e++)
            *(uint4*)&Xs[(e * 32 + sr) * 36 + sc4] = xp[e];
        #pragma unroll
        for (int e = 0; e < 2; e++)
            *(uint4*)&Ws[(e * 32 + sr) * 36 + sc4] = f2tf4(wp[e]);
    }

    for (int k0 = 0; k0 < DOUT_; k0 += 32) {
        const int cb = (k0 >> 5) & 1;
        __syncthreads();
        const bool more = (k0 + 32 < DOUT_);
        if (more) {
            #pragma unroll
            for (int e = 0; e < 4; e++) xp[e] = *xaddr(k0 + 32, e);
            #pragma unroll
            for (int e = 0; e < 2; e++)
                wp[e] = *(const float4*)&Wo[(size_t)(n0 + e * 32 + sr) * DOUT_ + k0 + 32 + sc4];
        }

        uint32_t* Xs = smo + cb * 4608;
        uint32_t* Ws = smo + 9216 + cb * 2304;

        uint32_t a[4][4];
        const int r0 = (16 * w + g) * 36, r1 = r0 + 8 * 36;
        #pragma unroll
        for (int kc = 0; kc < 4; kc++) {
            a[kc][0] = Xs[r0 + kc * 8 + t4];
            a[kc][1] = Xs[r1 + kc * 8 + t4];
            a[kc][2] = Xs[r0 + kc * 8 + t4 + 4];
            a[kc][3] = Xs[r1 + kc * 8 + t4 + 4];
        }
        #pragma unroll
        for (int kc = 0; kc < 4; kc++) {
            #pragma unroll
            for (int nc = 0; nc < 8; nc++) {
                const int br = (nc * 8 + g) * 36 + kc * 8;
                uint32_t b0 = Ws[br + t4];
                uint32_t b1 = Ws[br + t4 + 4];
                mma8(acc[nc], a[kc], b0, b1);
            }
        }

        if (more) {
            uint32_t* Xs2 = smo + (cb ^ 1) * 4608;
            uint32_t* Ws2 = smo + 9216 + (cb ^ 1) * 2304;
            #pragma unroll
            for (int e = 0; e < 4; e++)
                *(uint4*)&Xs2[(e * 32 + sr) * 36 + sc4] = xp[e];
            #pragma unroll
            for (int e = 0; e < 2; e++)
                *(uint4*)&Ws2[(e * 32 + sr) * 36 + sc4] = f2tf4(wp[e]);
        }
    }

    const int mA = m0 + 16 * w + g;
    float* rowA = out + (size_t)mA * DIN_ + n0;
    float* rowB = rowA + 8 * DIN_;
    #pragma unroll
    for (int nc = 0; nc < 8; nc++) {
        int col = nc * 8 + 2 * t4;
        float bx = bo[n0 + col], by = bo[n0 + col + 1];
        *(float2*)&rowA[col] = make_float2(acc[nc][0] + bx, acc[nc][1] + by);
        *(float2*)&rowB[col] = make_float2(acc[nc][2] + bx, acc[nc][3] + by);
    }
}

// ---------------------------------------------------------------------------
extern "C" void kernel_launch(void* const* d_in, const int* in_sizes, int n_in,
                              void* d_out, int out_size)
{
    const float* q  = (const float*)d_in[0];
    const float* k  = (const float*)d_in[1];
    const float* v  = (const float*)d_in[2];
    const float* Wq = (const float*)d_in[3];
    const float* bq = (const float*)d_in[4];
    const float* Wk = (const float*)d_in[5];
    const float* bk = (const float*)d_in[6];
    const float* Wv = (const float*)d_in[7];
    const float* bv = (const float*)d_in[8];
    const float* Wo = (const float*)d_in[9];
    const float* bo = (const float*)d_in[10];
    float* out = (float*)d_out;

    cudaFuncSetAttribute(proj_qk_kernel,
        cudaFuncAttributeMaxDynamicSharedMemorySize, PROJQK_SMEM_WORDS * 4);
    cudaFuncSetAttribute(proj_v_kernel,
        cudaFuncAttributeMaxDynamicSharedMemorySize, PROJV_SMEM_WORDS * 4);
    cudaFuncSetAttribute(attn_kernel,
        cudaFuncAttributeMaxDynamicSharedMemorySize, ATTN_SMEM_WORDS * 4);
    cudaFuncSetAttribute(outproj_kernel,
        cudaFuncAttributeMaxDynamicSharedMemorySize, OUTPROJ_SMEM_WORDS * 4);

    proj_qk_kernel<<<dim3(DOUT_ / 64, (B_ * T_) / 128, 2), 256,
                     PROJQK_SMEM_WORDS * 4>>>(q, k, Wq, bq, Wk, bk);
    proj_v_kernel<<<dim3(DOUT_ / 64, (B_ * T_) / 128), 256,
                    PROJV_SMEM_WORDS * 4>>>(v, Wv, bv);

    attn_kernel<<<dim3(BH_, T_ / 128), 256, ATTN_SMEM_WORDS * 4>>>();

    outproj_kernel<<<dim3(DIN_ / 64, (B_ * T_) / 128), 256,
                     OUTPROJ_SMEM_WORDS * 4>>>(Wo, bo, out);
}